// round 9
// baseline (speedup 1.0000x reference)
#include <cuda_runtime.h>
#include <cuda_bf16.h>
#include <cstdint>

#define Bb 4
#define Ss 2048
#define Dd 1024
#define Hh 16
#define DEPTH 64
#define BS (Bb * Ss)   // 8192
#define BH (Bb * Hh)   // 64

// ---------------- device scratch (allocation-free rule) ----------------
__device__ __nv_bfloat16 g_Wth[(size_t)Dd * Dd];         // W^T hi (reused)
__device__ __nv_bfloat16 g_Wtl[(size_t)Dd * Dd];         // W^T lo
__device__ __nv_bfloat16 g_Qh[(size_t)BH * Ss * DEPTH];  // [bh][s][64]
__device__ __nv_bfloat16 g_Ql[(size_t)BH * Ss * DEPTH];
__device__ __nv_bfloat16 g_Kh[(size_t)BH * Ss * DEPTH];
__device__ __nv_bfloat16 g_Kl[(size_t)BH * Ss * DEPTH];
__device__ __nv_bfloat16 g_Vth[(size_t)BH * DEPTH * Ss]; // V^T [bh][d][s]
__device__ __nv_bfloat16 g_Vtl[(size_t)BH * DEPTH * Ss];
__device__ __nv_bfloat16 g_Ch[(size_t)BS * Dd];          // ctx hi [b,s,1024]
__device__ __nv_bfloat16 g_Cl[(size_t)BS * Dd];
__device__ float2 g_stats[(size_t)BH * Ss];              // (rowmax, 1/rowsum)
__device__ float g_attn[(size_t)BH * Ss * Ss];           // fallback fp32 attn (1 GB)

// ---------------- mma.sync / ldmatrix helpers ----------------
__device__ __forceinline__ uint32_t smem_u32(const void* p) {
    uint32_t a;
    asm("{ .reg .u64 t; cvta.to.shared.u64 t, %1; cvt.u32.u64 %0, t; }" : "=r"(a) : "l"(p));
    return a;
}
__device__ __forceinline__ void ldsm_x4(uint32_t* r, uint32_t addr) {
    asm volatile("ldmatrix.sync.aligned.m8n8.x4.shared.b16 {%0,%1,%2,%3}, [%4];"
                 : "=r"(r[0]), "=r"(r[1]), "=r"(r[2]), "=r"(r[3]) : "r"(addr));
}
__device__ __forceinline__ void mma16816(float* d, const uint32_t* a, const uint32_t* b) {
    asm volatile(
        "mma.sync.aligned.m16n8k16.row.col.f32.bf16.bf16.f32 "
        "{%0,%1,%2,%3}, {%4,%5,%6,%7}, {%8,%9}, {%0,%1,%2,%3};"
        : "+f"(d[0]), "+f"(d[1]), "+f"(d[2]), "+f"(d[3])
        : "r"(a[0]), "r"(a[1]), "r"(a[2]), "r"(a[3]), "r"(b[0]), "r"(b[1]));
}
__device__ __forceinline__ void cvt8(const float* v, uint4& h4, uint4& l4) {
    __align__(16) __nv_bfloat16 h[8];
    __align__(16) __nv_bfloat16 l[8];
    #pragma unroll
    for (int i = 0; i < 8; i++) {
        h[i] = __float2bfloat16(v[i]);
        l[i] = __float2bfloat16(v[i] - __bfloat162float(h[i]));
    }
    h4 = *(uint4*)h;
    l4 = *(uint4*)l;
}

// ---------------- generic dense GEMM mainloop (unchanged from R8) ----------------
template <int NT, int ASRC>
__device__ __forceinline__ void gemm_core(
    const float* __restrict__ Af,
    const __nv_bfloat16* __restrict__ Ah, const __nv_bfloat16* __restrict__ Al, int lda,
    const __nv_bfloat16* __restrict__ Bh, const __nv_bfloat16* __restrict__ Bl, int ldb,
    int m0, int n0, int nChunks, char* smem,
    float (*acc)[4][4])
{
    constexpr int MI     = (NT == 128) ? 4 : 2;
    constexpr int OFF_AL = 16384;
    constexpr int OFF_BH = 32768;
    constexpr int OFF_BL = 32768 + NT * 128;

    const int tid = threadIdx.x, wid = tid >> 5, lane = tid & 31;
    const int wy = (NT == 128) ? (wid >> 2) : (wid >> 1);
    const int wx = (NT == 128) ? (wid & 3)  : (wid & 1);
    const int m0w = wy * MI * 16, n0w = wx * 32;
    const uint32_t sb = smem_u32(smem);

    for (int c = 0; c < nChunks; c++) {
        __syncthreads();
        const int kc = c * 64;
        #pragma unroll
        for (int i = 0; i < 4; i++) {
            int idx = tid + i * 256;
            int r = idx >> 3, sg = idx & 7;
            uint32_t off = (uint32_t)r * 128 + (((uint32_t)sg * 16) ^ (((uint32_t)(r & 7)) << 4));
            if (ASRC == 0) {
                const float* src = Af + (size_t)(m0 + r) * lda + kc + sg * 8;
                __align__(16) float v[8];
                *(float4*)v       = *(const float4*)src;
                *(float4*)(v + 4) = *(const float4*)(src + 4);
                uint4 h4, l4; cvt8(v, h4, l4);
                *(uint4*)(smem + off)          = h4;
                *(uint4*)(smem + OFF_AL + off) = l4;
            } else {
                size_t go = (size_t)(m0 + r) * lda + kc + sg * 8;
                *(uint4*)(smem + off)          = *(const uint4*)(Ah + go);
                *(uint4*)(smem + OFF_AL + off) = *(const uint4*)(Al + go);
            }
        }
        #pragma unroll
        for (int i = 0; i < NT / 32; i++) {
            int idx = tid + i * 256;
            int r = idx >> 3, sg = idx & 7;
            size_t go = (size_t)(n0 + r) * ldb + kc + sg * 8;
            uint32_t off = (uint32_t)r * 128 + (((uint32_t)sg * 16) ^ (((uint32_t)(r & 7)) << 4));
            *(uint4*)(smem + OFF_BH + off) = *(const uint4*)(Bh + go);
            *(uint4*)(smem + OFF_BL + off) = *(const uint4*)(Bl + go);
        }
        __syncthreads();

        #pragma unroll
        for (int ks = 0; ks < 4; ks++) {
            uint32_t ah[MI][4], al[MI][4];
            #pragma unroll
            for (int mi = 0; mi < MI; mi++) {
                int r = m0w + mi * 16 + (lane & 15);
                uint32_t kb = (uint32_t)ks * 32 + (((uint32_t)(lane >> 4)) << 4);
                uint32_t ad = sb + (uint32_t)r * 128 + (kb ^ (((uint32_t)(r & 7)) << 4));
                ldsm_x4(ah[mi], ad);
                ldsm_x4(al[mi], ad + OFF_AL);
            }
            #pragma unroll
            for (int nb = 0; nb < 2; nb++) {
                int n = n0w + nb * 16 + ((lane >> 4) << 3) + (lane & 7);
                uint32_t kb = (uint32_t)ks * 32 + (((uint32_t)((lane >> 3) & 1)) << 4);
                uint32_t bd = sb + OFF_BH + (uint32_t)n * 128 + (kb ^ (((uint32_t)(n & 7)) << 4));
                uint32_t bh[4], bl[4];
                ldsm_x4(bh, bd);
                ldsm_x4(bl, bd + NT * 128);
                #pragma unroll
                for (int mi = 0; mi < MI; mi++) {
                    mma16816(acc[mi][nb * 2],     ah[mi], bh);
                    mma16816(acc[mi][nb * 2 + 1], ah[mi], bh + 2);
                    mma16816(acc[mi][nb * 2],     ah[mi], bl);
                    mma16816(acc[mi][nb * 2 + 1], ah[mi], bl + 2);
                    mma16816(acc[mi][nb * 2],     al[mi], bh);
                    mma16816(acc[mi][nb * 2 + 1], al[mi], bh + 2);
                }
            }
        }
    }
}

static constexpr int SMEM_128 = 32768 + 2 * 128 * 128;  // 65536

// ---------------- projection GEMM (unchanged from R8) ----------------
template <int ASRC>
__global__ void __launch_bounds__(256, 2)
proj_kernel(const float* __restrict__ Af,
            const __nv_bfloat16* __restrict__ Ah, const __nv_bfloat16* __restrict__ Al,
            const __nv_bfloat16* __restrict__ Bh, const __nv_bfloat16* __restrict__ Bl,
            const float* __restrict__ bias, float* __restrict__ outF,
            __nv_bfloat16* __restrict__ oH, __nv_bfloat16* __restrict__ oL, int mode)
{
    extern __shared__ char smem[];
    int m0 = blockIdx.y * 128, n0 = blockIdx.x * 128;
    float acc[4][4][4] = {};
    gemm_core<128, ASRC>(Af, Ah, Al, 1024, Bh, Bl, 1024, m0, n0, 16, smem, acc);

    int tid = threadIdx.x, wid = tid >> 5, lane = tid & 31;
    int m0w = (wid >> 2) * 64, n0w = (wid & 3) * 32;
    #pragma unroll
    for (int mi = 0; mi < 4; mi++)
        #pragma unroll
        for (int nj = 0; nj < 4; nj++)
            #pragma unroll
            for (int e = 0; e < 4; e++) {
                int r  = m0 + m0w + mi * 16 + (lane >> 2) + (e >> 1) * 8;
                int cc = n0 + n0w + nj * 8 + (lane & 3) * 2 + (e & 1);
                float v = acc[mi][nj][e] + __ldg(bias + cc);
                if (mode == 0) {
                    outF[(size_t)r * Dd + cc] = v;
                } else {
                    __nv_bfloat16 hv = __float2bfloat16(v);
                    __nv_bfloat16 lv = __float2bfloat16(v - __bfloat162float(hv));
                    int b = r >> 11, s = r & 2047, h = cc >> 6, d = cc & 63;
                    size_t bh = (size_t)(b * Hh + h);
                    size_t idx = (mode == 1) ? ((bh * Ss + s) << 6) + d
                                             : (bh * DEPTH + d) * Ss + s;
                    oH[idx] = hv; oL[idx] = lv;
                }
            }
}

// ============ fused attention ============
// Shared QK tile MMA: Q in smem at sb_qh/sb_ql (128x64, 128B rows, swizzled),
// K tile at sb_kh/sb_kl. Warp layout 2x4, warp tile 64x32. 3-pass hi/lo.
__device__ __forceinline__ void qk_tile_mma(
    uint32_t sb_qh, uint32_t sb_ql, uint32_t sb_kh, uint32_t sb_kl,
    int lane, int m0w, int n0w, float acc[4][4][4])
{
    #pragma unroll
    for (int ks = 0; ks < 4; ks++) {
        uint32_t ah[4][4], al[4][4];
        #pragma unroll
        for (int mi = 0; mi < 4; mi++) {
            int r = m0w + mi * 16 + (lane & 15);
            uint32_t ch = (uint32_t)ks * 2 + (lane >> 4);
            uint32_t ad = (uint32_t)r * 128 + ((ch ^ (uint32_t)(r & 7)) << 4);
            ldsm_x4(ah[mi], sb_qh + ad);
            ldsm_x4(al[mi], sb_ql + ad);
        }
        #pragma unroll
        for (int nb = 0; nb < 2; nb++) {
            int n = n0w + nb * 16 + ((lane >> 4) << 3) + (lane & 7);
            uint32_t ch = (uint32_t)ks * 2 + ((lane >> 3) & 1);
            uint32_t bd = (uint32_t)n * 128 + ((ch ^ (uint32_t)(n & 7)) << 4);
            uint32_t bh[4], bl[4];
            ldsm_x4(bh, sb_kh + bd);
            ldsm_x4(bl, sb_kl + bd);
            #pragma unroll
            for (int mi = 0; mi < 4; mi++) {
                mma16816(acc[mi][nb * 2],     ah[mi], bh);
                mma16816(acc[mi][nb * 2 + 1], ah[mi], bh + 2);
                mma16816(acc[mi][nb * 2],     ah[mi], bl);
                mma16816(acc[mi][nb * 2 + 1], ah[mi], bl + 2);
                mma16816(acc[mi][nb * 2],     al[mi], bh);
                mma16816(acc[mi][nb * 2 + 1], al[mi], bh + 2);
            }
        }
    }
}

// stage a 128x64 bf16 hi/lo tile (rows of 128B, swizzled) from [row][64] K-major global
__device__ __forceinline__ void stage_64k(
    char* dst_h, char* dst_l,
    const __nv_bfloat16* __restrict__ srcH, const __nv_bfloat16* __restrict__ srcL,
    int row0, int tid)
{
    #pragma unroll
    for (int i = 0; i < 4; i++) {
        int idx = tid + i * 256;
        int r = idx >> 3, sg = idx & 7;
        size_t go = (size_t)(row0 + r) * 64 + sg * 8;
        uint32_t off = (uint32_t)r * 128 + (((uint32_t)sg ^ (uint32_t)(r & 7)) << 4);
        *(uint4*)(dst_h + off) = *(const uint4*)(srcH + go);
        *(uint4*)(dst_l + off) = *(const uint4*)(srcL + go);
    }
}

// ---------------- kernel 1: row stats (online max / sumexp) ----------------
// smem: QH 0 | QL 16K | KH 32K | KL 48K | RED 64K(2K) | MARR(512) | STM(512) | STS(512)
static constexpr int K1_RED  = 65536;
static constexpr int K1_MARR = 67584;
static constexpr int K1_STM  = 68096;
static constexpr int K1_STS  = 68608;
static constexpr int SMEM_K1 = 69120;

__global__ void __launch_bounds__(256, 2)
stats_kernel(const __nv_bfloat16* __restrict__ Qh, const __nv_bfloat16* __restrict__ Ql,
             const __nv_bfloat16* __restrict__ Kh, const __nv_bfloat16* __restrict__ Kl,
             const float* __restrict__ mask, float2* __restrict__ stats)
{
    extern __shared__ char smem[];
    const uint32_t sb = smem_u32(smem);
    const int tid = threadIdx.x, wid = tid >> 5, lane = tid & 31;
    const int wy = wid >> 2, wx = wid & 3;
    const int m0w = wy * 64, n0w = wx * 32;
    const int bh = blockIdx.y, m0 = blockIdx.x * 128;
    const size_t ho = (size_t)bh * Ss * DEPTH;

    float* RED  = (float*)(smem + K1_RED);
    float* MARR = (float*)(smem + K1_MARR);
    float* STM  = (float*)(smem + K1_STM);
    float* STS  = (float*)(smem + K1_STS);

    stage_64k(smem, smem + 16384, Qh + ho, Ql + ho, m0, tid);
    if (tid < 128) { STM[tid] = -1e30f; STS[tid] = 0.f; }
    __syncthreads();

    for (int t = 0; t < 16; t++) {
        const int sk0 = t * 128;
        stage_64k(smem + 32768, smem + 49152, Kh + ho, Kl + ho, sk0, tid);
        __syncthreads();

        float acc[4][4][4] = {};
        qk_tile_mma(sb, sb + 16384, sb + 32768, sb + 49152, lane, m0w, n0w, acc);

        // scale + mask (store masked logits back into acc)
        #pragma unroll
        for (int mi = 0; mi < 4; mi++)
            #pragma unroll
            for (int h = 0; h < 2; h++) {
                int sq = m0 + m0w + mi * 16 + (lane >> 2) + h * 8;
                #pragma unroll
                for (int nj = 0; nj < 4; nj++) {
                    int sk = sk0 + n0w + nj * 8 + (lane & 3) * 2;
                    acc[mi][nj][h * 2]     = acc[mi][nj][h * 2]     * 0.125f
                        + __ldg(mask + (size_t)sq * Ss + sk) * -1e9f;
                    acc[mi][nj][h * 2 + 1] = acc[mi][nj][h * 2 + 1] * 0.125f
                        + __ldg(mask + (size_t)sq * Ss + sk + 1) * -1e9f;
                }
            }

        // per-row tile max
        float pm[4][2];
        #pragma unroll
        for (int mi = 0; mi < 4; mi++)
            #pragma unroll
            for (int h = 0; h < 2; h++) {
                float m = -1e30f;
                #pragma unroll
                for (int nj = 0; nj < 4; nj++) {
                    m = fmaxf(m, acc[mi][nj][h * 2]);
                    m = fmaxf(m, acc[mi][nj][h * 2 + 1]);
                }
                m = fmaxf(m, __shfl_xor_sync(0xffffffffu, m, 1));
                m = fmaxf(m, __shfl_xor_sync(0xffffffffu, m, 2));
                pm[mi][h] = m;
            }
        if ((lane & 3) == 0) {
            #pragma unroll
            for (int mi = 0; mi < 4; mi++)
                #pragma unroll
                for (int h = 0; h < 2; h++) {
                    int row = m0w + mi * 16 + (lane >> 2) + h * 8;
                    RED[wx * 128 + row] = pm[mi][h];
                }
        }
        __syncthreads();

        float m_old = 0.f, m_new = 0.f;
        if (tid < 128) {
            float tm = fmaxf(fmaxf(RED[tid], RED[128 + tid]),
                             fmaxf(RED[256 + tid], RED[384 + tid]));
            m_old = STM[tid];
            m_new = fmaxf(m_old, tm);
            MARR[tid] = m_new;
        }
        __syncthreads();

        // per-row tile sum of exp(v - m_new)
        float ps[4][2];
        #pragma unroll
        for (int mi = 0; mi < 4; mi++)
            #pragma unroll
            for (int h = 0; h < 2; h++) {
                int row = m0w + mi * 16 + (lane >> 2) + h * 8;
                float mn = MARR[row];
                float s = 0.f;
                #pragma unroll
                for (int nj = 0; nj < 4; nj++) {
                    s += __expf(acc[mi][nj][h * 2]     - mn);
                    s += __expf(acc[mi][nj][h * 2 + 1] - mn);
                }
                s += __shfl_xor_sync(0xffffffffu, s, 1);
                s += __shfl_xor_sync(0xffffffffu, s, 2);
                ps[mi][h] = s;
            }
        if ((lane & 3) == 0) {
            #pragma unroll
            for (int mi = 0; mi < 4; mi++)
                #pragma unroll
                for (int h = 0; h < 2; h++) {
                    int row = m0w + mi * 16 + (lane >> 2) + h * 8;
                    RED[wx * 128 + row] = ps[mi][h];
                }
        }
        __syncthreads();
        if (tid < 128) {
            float tsum = RED[tid] + RED[128 + tid] + RED[256 + tid] + RED[384 + tid];
            STS[tid] = STS[tid] * __expf(m_old - m_new) + tsum;
            STM[tid] = m_new;
        }
        __syncthreads();
    }

    if (tid < 128)
        stats[(size_t)bh * Ss + m0 + tid] = make_float2(STM[tid], 1.0f / STS[tid]);
}

// ---------------- kernel 2: fused probs + ctx ----------------
// smem: QH 0 | QL 16K | KH 32K | KL 48K | VH 64K | VL 80K | PH 96K | PL 128K | STATS 160K
static constexpr int K2_VH = 65536;
static constexpr int K2_VL = 81920;
static constexpr int K2_PH = 98304;
static constexpr int K2_PL = 131072;
static constexpr int K2_ST = 163840;
static constexpr int SMEM_K2 = 164864;

__global__ void __launch_bounds__(256)
attn_fused_kernel(const __nv_bfloat16* __restrict__ Qh, const __nv_bfloat16* __restrict__ Ql,
                  const __nv_bfloat16* __restrict__ Kh, const __nv_bfloat16* __restrict__ Kl,
                  const __nv_bfloat16* __restrict__ Vth, const __nv_bfloat16* __restrict__ Vtl,
                  const float* __restrict__ mask, const float2* __restrict__ stats,
                  float* __restrict__ attn,
                  __nv_bfloat16* __restrict__ Ch, __nv_bfloat16* __restrict__ Cl)
{
    extern __shared__ char smem[];
    const uint32_t sb = smem_u32(smem);
    const int tid = threadIdx.x, wid = tid >> 5, lane = tid & 31;
    const int wy = wid >> 2, wx = wid & 3;
    const int m0w = wy * 64, n0w = wx * 32;            // QK layout
    const int m0w2 = (wid >> 1) * 32, n0w2 = (wid & 1) * 32;  // PV layout
    const int bh = blockIdx.y, m0 = blockIdx.x * 128;
    const int b = bh >> 4, hh = bh & 15;
    const size_t ho = (size_t)bh * Ss * DEPTH;
    const size_t vo = (size_t)bh * DEPTH * Ss;
    float2* sm_stats = (float2*)(smem + K2_ST);

    stage_64k(smem, smem + 16384, Qh + ho, Ql + ho, m0, tid);
    if (tid < 128) sm_stats[tid] = stats[(size_t)bh * Ss + m0 + tid];
    __syncthreads();

    float acc2[2][4][4] = {};   // ctx accumulator 128x64 / 8 warps

    for (int t = 0; t < 16; t++) {
        const int sk0 = t * 128;
        // stage K tile
        stage_64k(smem + 32768, smem + 49152, Kh + ho, Kl + ho, sk0, tid);
        // stage V^T slice: 64 d-rows x 128 sk, rows of 256B swizzled
        #pragma unroll
        for (int i = 0; i < 4; i++) {
            int idx = tid + i * 256;
            int d = idx >> 4, ch = idx & 15;
            size_t go = vo + (size_t)d * Ss + sk0 + ch * 8;
            uint32_t off = (uint32_t)d * 256 + (((uint32_t)ch ^ (uint32_t)(d & 7)) << 4);
            *(uint4*)(smem + K2_VH + off) = *(const uint4*)(Vth + go);
            *(uint4*)(smem + K2_VL + off) = *(const uint4*)(Vtl + go);
        }
        __syncthreads();

        // QK tile
        float acc[4][4][4] = {};
        qk_tile_mma(sb, sb + 16384, sb + 32768, sb + 49152, lane, m0w, n0w, acc);

        // epilogue: probs -> global fp32 + smem bf16 hi/lo
        #pragma unroll
        for (int mi = 0; mi < 4; mi++)
            #pragma unroll
            for (int h = 0; h < 2; h++) {
                int rl = m0w + mi * 16 + (lane >> 2) + h * 8;
                float2 st = sm_stats[rl];
                int sq = m0 + rl;
                #pragma unroll
                for (int nj = 0; nj < 4; nj++) {
                    int cl = n0w + nj * 8 + (lane & 3) * 2;
                    int sk = sk0 + cl;
                    float v0 = acc[mi][nj][h * 2] * 0.125f
                             + __ldg(mask + (size_t)sq * Ss + sk) * -1e9f;
                    float v1 = acc[mi][nj][h * 2 + 1] * 0.125f
                             + __ldg(mask + (size_t)sq * Ss + sk + 1) * -1e9f;
                    float p0 = __expf(v0 - st.x) * st.y;
                    float p1 = __expf(v1 - st.x) * st.y;
                    *(float2*)(attn + ((size_t)bh * Ss + sq) * Ss + sk) = make_float2(p0, p1);
                    __nv_bfloat16 h0 = __float2bfloat16(p0);
                    __nv_bfloat16 h1 = __float2bfloat16(p1);
                    __nv_bfloat16 l0 = __float2bfloat16(p0 - __bfloat162float(h0));
                    __nv_bfloat16 l1 = __float2bfloat16(p1 - __bfloat162float(h1));
                    uint32_t off = (uint32_t)rl * 256
                                 + ((((uint32_t)cl >> 3) ^ (uint32_t)(rl & 7)) << 4)
                                 + ((uint32_t)cl & 7) * 2;
                    *(__nv_bfloat162*)(smem + K2_PH + off) = __halves2bfloat162(h0, h1);
                    *(__nv_bfloat162*)(smem + K2_PL + off) = __halves2bfloat162(l0, l1);
                }
            }
        __syncthreads();

        // PV tile: ctx += P(128x128) x V^T(64x128)
        #pragma unroll
        for (int ks = 0; ks < 8; ks++) {
            uint32_t pa_h[2][4], pa_l[2][4];
            #pragma unroll
            for (int mi = 0; mi < 2; mi++) {
                int r = m0w2 + mi * 16 + (lane & 15);
                uint32_t ch = (uint32_t)ks * 2 + (lane >> 4);
                uint32_t ad = (uint32_t)r * 256 + ((ch ^ (uint32_t)(r & 7)) << 4);
                ldsm_x4(pa_h[mi], sb + K2_PH + ad);
                ldsm_x4(pa_l[mi], sb + K2_PL + ad);
            }
            #pragma unroll
            for (int nbj = 0; nbj < 2; nbj++) {
                int n = n0w2 + nbj * 16 + ((lane >> 4) << 3) + (lane & 7);
                uint32_t ch = (uint32_t)ks * 2 + ((lane >> 3) & 1);
                uint32_t bd = (uint32_t)n * 256 + ((ch ^ (uint32_t)(n & 7)) << 4);
                uint32_t vh[4], vl[4];
                ldsm_x4(vh, sb + K2_VH + bd);
                ldsm_x4(vl, sb + K2_VL + bd);
                #pragma unroll
                for (int mi = 0; mi < 2; mi++) {
                    mma16816(acc2[mi][nbj * 2],     pa_h[mi], vh);
                    mma16816(acc2[mi][nbj * 2 + 1], pa_h[mi], vh + 2);
                    mma16816(acc2[mi][nbj * 2],     pa_h[mi], vl);
                    mma16816(acc2[mi][nbj * 2 + 1], pa_h[mi], vl + 2);
                    mma16816(acc2[mi][nbj * 2],     pa_l[mi], vh);
                    mma16816(acc2[mi][nbj * 2 + 1], pa_l[mi], vh + 2);
                }
            }
        }
        __syncthreads();
    }

    // ctx epilogue -> bf16 hi/lo [b,s,1024]
    #pragma unroll
    for (int mi = 0; mi < 2; mi++)
        #pragma unroll
        for (int nj = 0; nj < 4; nj++)
            #pragma unroll
            for (int e = 0; e < 4; e++) {
                int s = m0 + m0w2 + mi * 16 + (lane >> 2) + (e >> 1) * 8;
                int d = n0w2 + nj * 8 + (lane & 3) * 2 + (e & 1);
                float v = acc2[mi][nj][e];
                __nv_bfloat16 hv = __float2bfloat16(v);
                __nv_bfloat16 lv = __float2bfloat16(v - __bfloat162float(hv));
                size_t idx = ((size_t)(b * Ss + s)) * Dd + hh * DEPTH + d;
                Ch[idx] = hv; Cl[idx] = lv;
            }
}

// ---------------- W transpose + hi/lo split ----------------
__global__ void transpose_conv_kernel(const float* __restrict__ W,
                                      __nv_bfloat16* __restrict__ Th,
                                      __nv_bfloat16* __restrict__ Tl)
{
    __shared__ float t[32][33];
    int tx = threadIdx.x, ty = threadIdx.y;
    int x = blockIdx.x * 32 + tx;
    int y = blockIdx.y * 32 + ty;
    t[ty][tx] = W[(size_t)y * Dd + x];
    __syncthreads();
    int n = blockIdx.x * 32 + ty;
    int k = blockIdx.y * 32 + tx;
    float v = t[tx][ty];
    __nv_bfloat16 hv = __float2bfloat16(v);
    Th[(size_t)n * Dd + k] = hv;
    Tl[(size_t)n * Dd + k] = __float2bfloat16(v - __bfloat162float(hv));
}

// ---------------------------------------------------------------------------
extern "C" void kernel_launch(void* const* d_in, const int* in_sizes, int n_in,
                              void* d_out, int out_size) {
    const float* q    = (const float*)d_in[0];
    const float* k    = (const float*)d_in[1];
    const float* v    = (const float*)d_in[2];
    const float* mask = (const float*)d_in[3];
    const float* Wq   = (const float*)d_in[4];
    const float* bq   = (const float*)d_in[5];
    const float* Wk   = (const float*)d_in[6];
    const float* bk   = (const float*)d_in[7];
    const float* Wv   = (const float*)d_in[8];
    const float* bv   = (const float*)d_in[9];
    const float* Wo   = (const float*)d_in[10];
    const float* bo   = (const float*)d_in[11];
    float* out = (float*)d_out;

    const size_t OUT_ELEMS  = (size_t)BS * Dd;
    const size_t ATTN_ELEMS = (size_t)BH * Ss * Ss;

    float* attnbuf = nullptr;
    cudaGetSymbolAddress((void**)&attnbuf, g_attn);
    if ((size_t)out_size >= OUT_ELEMS + ATTN_ELEMS) attnbuf = out + OUT_ELEMS;

    __nv_bfloat16 *dWth, *dWtl, *dQh, *dQl, *dKh, *dKl, *dVth, *dVtl, *dCh, *dCl;
    float2* dStats;
    cudaGetSymbolAddress((void**)&dWth, g_Wth);
    cudaGetSymbolAddress((void**)&dWtl, g_Wtl);
    cudaGetSymbolAddress((void**)&dQh,  g_Qh);
    cudaGetSymbolAddress((void**)&dQl,  g_Ql);
    cudaGetSymbolAddress((void**)&dKh,  g_Kh);
    cudaGetSymbolAddress((void**)&dKl,  g_Kl);
    cudaGetSymbolAddress((void**)&dVth, g_Vth);
    cudaGetSymbolAddress((void**)&dVtl, g_Vtl);
    cudaGetSymbolAddress((void**)&dCh,  g_Ch);
    cudaGetSymbolAddress((void**)&dCl,  g_Cl);
    cudaGetSymbolAddress((void**)&dStats, g_stats);

    cudaFuncSetAttribute(proj_kernel<0>,    cudaFuncAttributeMaxDynamicSharedMemorySize, SMEM_128);
    cudaFuncSetAttribute(proj_kernel<1>,    cudaFuncAttributeMaxDynamicSharedMemorySize, SMEM_128);
    cudaFuncSetAttribute(stats_kernel,      cudaFuncAttributeMaxDynamicSharedMemorySize, SMEM_K1);
    cudaFuncSetAttribute(attn_fused_kernel, cudaFuncAttributeMaxDynamicSharedMemorySize, SMEM_K2);

    dim3 tposeBlk(32, 32), tposeGrid(32, 32);
    dim3 projGrid(8, 64);

    transpose_conv_kernel<<<tposeGrid, tposeBlk>>>(Wq, dWth, dWtl);
    proj_kernel<0><<<projGrid, 256, SMEM_128>>>(q, nullptr, nullptr, dWth, dWtl,
                                                bq, nullptr, dQh, dQl, 1);
    transpose_conv_kernel<<<tposeGrid, tposeBlk>>>(Wk, dWth, dWtl);
    proj_kernel<0><<<projGrid, 256, SMEM_128>>>(k, nullptr, nullptr, dWth, dWtl,
                                                bk, nullptr, dKh, dKl, 1);
    transpose_conv_kernel<<<tposeGrid, tposeBlk>>>(Wv, dWth, dWtl);
    proj_kernel<0><<<projGrid, 256, SMEM_128>>>(v, nullptr, nullptr, dWth, dWtl,
                                                bv, nullptr, dVth, dVtl, 2);

    stats_kernel<<<dim3(16, 64), 256, SMEM_K1>>>(dQh, dQl, dKh, dKl, mask, dStats);
    attn_fused_kernel<<<dim3(16, 64), 256, SMEM_K2>>>(dQh, dQl, dKh, dKl, dVth, dVtl,
                                                      mask, dStats, attnbuf, dCh, dCl);

    transpose_conv_kernel<<<tposeGrid, tposeBlk>>>(Wo, dWth, dWtl);
    proj_kernel<1><<<projGrid, 256, SMEM_128>>>(nullptr, dCh, dCl, dWth, dWtl,
                                                bo, out, nullptr, nullptr, 0);
}

// round 10
// speedup vs baseline: 1.1550x; 1.1550x over previous
#include <cuda_runtime.h>
#include <cuda_bf16.h>
#include <cstdint>

#define Bb 4
#define Ss 2048
#define Dd 1024
#define Hh 16
#define DEPTH 64
#define BS (Bb * Ss)   // 8192
#define BH (Bb * Hh)   // 64

// ---------------- device scratch (allocation-free rule) ----------------
__device__ __nv_bfloat16 g_Wth[(size_t)Dd * Dd];         // W^T hi (reused)
__device__ __nv_bfloat16 g_Wtl[(size_t)Dd * Dd];         // W^T lo
__device__ __nv_bfloat16 g_Qh[(size_t)BH * Ss * DEPTH];  // [bh][s][64]
__device__ __nv_bfloat16 g_Ql[(size_t)BH * Ss * DEPTH];
__device__ __nv_bfloat16 g_Kh[(size_t)BH * Ss * DEPTH];
__device__ __nv_bfloat16 g_Kl[(size_t)BH * Ss * DEPTH];
__device__ __nv_bfloat16 g_Vth[(size_t)BH * DEPTH * Ss]; // V^T [bh][d][s]
__device__ __nv_bfloat16 g_Vtl[(size_t)BH * DEPTH * Ss];
__device__ __nv_bfloat16 g_Ch[(size_t)BS * Dd];          // ctx hi [b,s,1024]
__device__ __nv_bfloat16 g_Cl[(size_t)BS * Dd];
__device__ float g_inv[(size_t)BH * Ss];                 // 1/rowsum
__device__ float g_attn[(size_t)BH * Ss * Ss];           // fallback fp32 attn (1 GB)

// ---------------- PTX helpers ----------------
__device__ __forceinline__ uint32_t smem_u32(const void* p) {
    uint32_t a;
    asm("{ .reg .u64 t; cvta.to.shared.u64 t, %1; cvt.u32.u64 %0, t; }" : "=r"(a) : "l"(p));
    return a;
}
__device__ __forceinline__ void ldsm_x4(uint32_t* r, uint32_t addr) {
    asm volatile("ldmatrix.sync.aligned.m8n8.x4.shared.b16 {%0,%1,%2,%3}, [%4];"
                 : "=r"(r[0]), "=r"(r[1]), "=r"(r[2]), "=r"(r[3]) : "r"(addr));
}
__device__ __forceinline__ void mma16816(float* d, const uint32_t* a, const uint32_t* b) {
    asm volatile(
        "mma.sync.aligned.m16n8k16.row.col.f32.bf16.bf16.f32 "
        "{%0,%1,%2,%3}, {%4,%5,%6,%7}, {%8,%9}, {%0,%1,%2,%3};"
        : "+f"(d[0]), "+f"(d[1]), "+f"(d[2]), "+f"(d[3])
        : "r"(a[0]), "r"(a[1]), "r"(a[2]), "r"(a[3]), "r"(b[0]), "r"(b[1]));
}
__device__ __forceinline__ void cpa16(uint32_t dst, const void* src) {
    asm volatile("cp.async.cg.shared.global [%0], [%1], 16;" :: "r"(dst), "l"(src));
}
__device__ __forceinline__ void cpa_commit() {
    asm volatile("cp.async.commit_group;" ::: "memory");
}
template <int N>
__device__ __forceinline__ void cpa_wait() {
    asm volatile("cp.async.wait_group %0;" :: "n"(N) : "memory");
}
__device__ __forceinline__ void cvt8(const float* v, uint4& h4, uint4& l4) {
    __align__(16) __nv_bfloat16 h[8];
    __align__(16) __nv_bfloat16 l[8];
    #pragma unroll
    for (int i = 0; i < 8; i++) {
        h[i] = __float2bfloat16(v[i]);
        l[i] = __float2bfloat16(v[i] - __bfloat162float(h[i]));
    }
    h4 = *(uint4*)h;
    l4 = *(uint4*)l;
}

// ---------------- dense GEMM mainloop with cp.async double-buffered B ----------
// A: [M rows][K] K-major (fp32 inline-split if ASRC==0, else bf16 hi/lo).
// B: [128 rows][K] K-major bf16 hi/lo. K chunks of 64 (128B swizzled rows).
// smem: A hi 0..16K, A lo 16K..32K, B buf0 32K..64K (hi 16K, lo 16K), B buf1 64K..96K.
template <int ASRC>
__device__ __forceinline__ void gemm_core(
    const float* __restrict__ Af,
    const __nv_bfloat16* __restrict__ Ah, const __nv_bfloat16* __restrict__ Al, int lda,
    const __nv_bfloat16* __restrict__ Bh, const __nv_bfloat16* __restrict__ Bl, int ldb,
    int m0, int n0, int nChunks, char* smem,
    float (*acc)[4][4])
{
    constexpr int OFF_AL = 16384;
    constexpr int OFF_B  = 32768;
    constexpr int BSZ    = 32768;   // hi+lo per buffer

    const int tid = threadIdx.x, wid = tid >> 5, lane = tid & 31;
    const int m0w = (wid >> 2) * 64, n0w = (wid & 3) * 32;
    const uint32_t sb = smem_u32(smem);

    auto issueB = [&](int c, int buf) {
        uint32_t base = sb + OFF_B + buf * BSZ;
        #pragma unroll
        for (int i = 0; i < 4; i++) {
            int idx = tid + i * 256;
            int r = idx >> 3, sg = idx & 7;
            size_t go = (size_t)(n0 + r) * ldb + c * 64 + sg * 8;
            uint32_t off = (uint32_t)r * 128 + (((uint32_t)sg * 16) ^ (((uint32_t)(r & 7)) << 4));
            cpa16(base + off,         Bh + go);
            cpa16(base + 16384 + off, Bl + go);
        }
        cpa_commit();
    };

    issueB(0, 0);

    for (int c = 0; c < nChunks; c++) {
        const int buf = c & 1;
        __syncthreads();
        const int kc = c * 64;
        // stage A (plain path; fp32 conversion inline if ASRC==0)
        #pragma unroll
        for (int i = 0; i < 4; i++) {
            int idx = tid + i * 256;
            int r = idx >> 3, sg = idx & 7;
            uint32_t off = (uint32_t)r * 128 + (((uint32_t)sg * 16) ^ (((uint32_t)(r & 7)) << 4));
            if (ASRC == 0) {
                const float* src = Af + (size_t)(m0 + r) * lda + kc + sg * 8;
                __align__(16) float v[8];
                *(float4*)v       = *(const float4*)src;
                *(float4*)(v + 4) = *(const float4*)(src + 4);
                uint4 h4, l4; cvt8(v, h4, l4);
                *(uint4*)(smem + off)          = h4;
                *(uint4*)(smem + OFF_AL + off) = l4;
            } else {
                size_t go = (size_t)(m0 + r) * lda + kc + sg * 8;
                *(uint4*)(smem + off)          = *(const uint4*)(Ah + go);
                *(uint4*)(smem + OFF_AL + off) = *(const uint4*)(Al + go);
            }
        }
        if (c + 1 < nChunks) { issueB(c + 1, buf ^ 1); cpa_wait<1>(); }
        else                 { cpa_wait<0>(); }
        __syncthreads();

        const uint32_t bbase = sb + OFF_B + buf * BSZ;
        #pragma unroll
        for (int ks = 0; ks < 4; ks++) {
            uint32_t ah[4][4], al[4][4];
            #pragma unroll
            for (int mi = 0; mi < 4; mi++) {
                int r = m0w + mi * 16 + (lane & 15);
                uint32_t kb = (uint32_t)ks * 32 + (((uint32_t)(lane >> 4)) << 4);
                uint32_t ad = sb + (uint32_t)r * 128 + (kb ^ (((uint32_t)(r & 7)) << 4));
                ldsm_x4(ah[mi], ad);
                ldsm_x4(al[mi], ad + OFF_AL);
            }
            #pragma unroll
            for (int nb = 0; nb < 2; nb++) {
                int n = n0w + nb * 16 + ((lane >> 4) << 3) + (lane & 7);
                uint32_t kb = (uint32_t)ks * 32 + (((uint32_t)((lane >> 3) & 1)) << 4);
                uint32_t bd = bbase + (uint32_t)n * 128 + (kb ^ (((uint32_t)(n & 7)) << 4));
                uint32_t bh[4], bl[4];
                ldsm_x4(bh, bd);
                ldsm_x4(bl, bd + 16384);
                #pragma unroll
                for (int mi = 0; mi < 4; mi++) {
                    mma16816(acc[mi][nb * 2],     ah[mi], bh);
                    mma16816(acc[mi][nb * 2 + 1], ah[mi], bh + 2);
                    mma16816(acc[mi][nb * 2],     ah[mi], bl);
                    mma16816(acc[mi][nb * 2 + 1], ah[mi], bl + 2);
                    mma16816(acc[mi][nb * 2],     al[mi], bh);
                    mma16816(acc[mi][nb * 2 + 1], al[mi], bh + 2);
                }
            }
        }
    }
}

static constexpr int SMEM_PROJ = 98304;  // A 32K + B double 64K

// ---------------- projection GEMM ----------------
template <int ASRC>
__global__ void __launch_bounds__(256, 2)
proj_kernel(const float* __restrict__ Af,
            const __nv_bfloat16* __restrict__ Ah, const __nv_bfloat16* __restrict__ Al,
            const __nv_bfloat16* __restrict__ Bh, const __nv_bfloat16* __restrict__ Bl,
            const float* __restrict__ bias, float* __restrict__ outF,
            __nv_bfloat16* __restrict__ oH, __nv_bfloat16* __restrict__ oL, int mode)
{
    extern __shared__ char smem[];
    int m0 = blockIdx.y * 128, n0 = blockIdx.x * 128;
    float acc[4][4][4] = {};
    gemm_core<ASRC>(Af, Ah, Al, 1024, Bh, Bl, 1024, m0, n0, 16, smem, acc);

    int tid = threadIdx.x, wid = tid >> 5, lane = tid & 31;
    int m0w = (wid >> 2) * 64, n0w = (wid & 3) * 32;
    #pragma unroll
    for (int mi = 0; mi < 4; mi++)
        #pragma unroll
        for (int nj = 0; nj < 4; nj++)
            #pragma unroll
            for (int e = 0; e < 4; e++) {
                int r  = m0 + m0w + mi * 16 + (lane >> 2) + (e >> 1) * 8;
                int cc = n0 + n0w + nj * 8 + (lane & 3) * 2 + (e & 1);
                float v = acc[mi][nj][e] + __ldg(bias + cc);
                if (mode == 0) {
                    outF[(size_t)r * Dd + cc] = v;
                } else {
                    __nv_bfloat16 hv = __float2bfloat16(v);
                    __nv_bfloat16 lv = __float2bfloat16(v - __bfloat162float(hv));
                    int b = r >> 11, s = r & 2047, h = cc >> 6, d = cc & 63;
                    size_t bh = (size_t)(b * Hh + h);
                    size_t idx = (mode == 1) ? ((bh * Ss + s) << 6) + d
                                             : (bh * DEPTH + d) * Ss + s;
                    oH[idx] = hv; oL[idx] = lv;
                }
            }
}

// ============ fused attention (single QK pass, max-free softmax) ============
// smem layout:
//   QH 0 (16K) | QL 16384
//   K buf0 32768 (hi 16K, lo 16K) | K buf1 65536
//   V buf0 98304 (hi 16K, lo 16K) | V buf1 131072
//   PH 163840 (32K) | PL 196608 (32K)
//   RED 229376 (2K) | SUM 231424 (512)   total 231936
static constexpr int F_K0  = 32768;
static constexpr int F_V0  = 98304;
static constexpr int F_PH  = 163840;
static constexpr int F_PL  = 196608;
static constexpr int F_RED = 229376;
static constexpr int F_SUM = 231424;
static constexpr int SMEM_FUSED = 231936;

__device__ __forceinline__ void qk_tile_mma(
    uint32_t sb_qh, uint32_t sb_ql, uint32_t sb_kh, uint32_t sb_kl,
    int lane, int m0w, int n0w, float acc[4][4][4])
{
    #pragma unroll
    for (int ks = 0; ks < 4; ks++) {
        uint32_t ah[4][4], al[4][4];
        #pragma unroll
        for (int mi = 0; mi < 4; mi++) {
            int r = m0w + mi * 16 + (lane & 15);
            uint32_t ch = (uint32_t)ks * 2 + (lane >> 4);
            uint32_t ad = (uint32_t)r * 128 + ((ch ^ (uint32_t)(r & 7)) << 4);
            ldsm_x4(ah[mi], sb_qh + ad);
            ldsm_x4(al[mi], sb_ql + ad);
        }
        #pragma unroll
        for (int nb = 0; nb < 2; nb++) {
            int n = n0w + nb * 16 + ((lane >> 4) << 3) + (lane & 7);
            uint32_t ch = (uint32_t)ks * 2 + ((lane >> 3) & 1);
            uint32_t bd = (uint32_t)n * 128 + ((ch ^ (uint32_t)(n & 7)) << 4);
            uint32_t bh[4], bl[4];
            ldsm_x4(bh, sb_kh + bd);
            ldsm_x4(bl, sb_kl + bd);
            #pragma unroll
            for (int mi = 0; mi < 4; mi++) {
                mma16816(acc[mi][nb * 2],     ah[mi], bh);
                mma16816(acc[mi][nb * 2 + 1], ah[mi], bh + 2);
                mma16816(acc[mi][nb * 2],     ah[mi], bl);
                mma16816(acc[mi][nb * 2 + 1], ah[mi], bl + 2);
                mma16816(acc[mi][nb * 2],     al[mi], bh);
                mma16816(acc[mi][nb * 2 + 1], al[mi], bh + 2);
            }
        }
    }
}

__global__ void __launch_bounds__(256)
attn_fused_kernel(const __nv_bfloat16* __restrict__ Qh, const __nv_bfloat16* __restrict__ Ql,
                  const __nv_bfloat16* __restrict__ Kh, const __nv_bfloat16* __restrict__ Kl,
                  const __nv_bfloat16* __restrict__ Vth, const __nv_bfloat16* __restrict__ Vtl,
                  const float* __restrict__ mask,
                  float* __restrict__ attn, float* __restrict__ invsum,
                  __nv_bfloat16* __restrict__ Ch, __nv_bfloat16* __restrict__ Cl)
{
    extern __shared__ char smem[];
    const uint32_t sb = smem_u32(smem);
    const int tid = threadIdx.x, wid = tid >> 5, lane = tid & 31;
    const int m0w = (wid >> 2) * 64, n0w = (wid & 3) * 32;        // QK layout
    const int m0w2 = (wid >> 1) * 32, n0w2 = (wid & 1) * 32;      // PV layout
    const int bh = blockIdx.y, m0 = blockIdx.x * 128;
    const int b = bh >> 4, hh = bh & 15;
    const __nv_bfloat16* Kh_ = Kh + (size_t)bh * Ss * DEPTH;
    const __nv_bfloat16* Kl_ = Kl + (size_t)bh * Ss * DEPTH;
    const __nv_bfloat16* Vh_ = Vth + (size_t)bh * DEPTH * Ss;
    const __nv_bfloat16* Vl_ = Vtl + (size_t)bh * DEPTH * Ss;
    float* RED = (float*)(smem + F_RED);
    float* SUM = (float*)(smem + F_SUM);

    auto issueKV = [&](int t1, int buf) {
        const int sk0n = t1 * 128;
        uint32_t kb = sb + F_K0 + buf * 32768;
        uint32_t vb = sb + F_V0 + buf * 32768;
        #pragma unroll
        for (int i = 0; i < 4; i++) {
            int idx = tid + i * 256;
            int r = idx >> 3, sg = idx & 7;
            size_t go = (size_t)(sk0n + r) * 64 + sg * 8;
            uint32_t off = (uint32_t)r * 128 + (((uint32_t)sg ^ (uint32_t)(r & 7)) << 4);
            cpa16(kb + off,         Kh_ + go);
            cpa16(kb + 16384 + off, Kl_ + go);
        }
        #pragma unroll
        for (int i = 0; i < 4; i++) {
            int idx = tid + i * 256;
            int d = idx >> 4, ch = idx & 15;
            size_t go = (size_t)d * Ss + sk0n + ch * 8;
            uint32_t off = (uint32_t)d * 256 + (((uint32_t)ch ^ (uint32_t)(d & 7)) << 4);
            cpa16(vb + off,         Vh_ + go);
            cpa16(vb + 16384 + off, Vl_ + go);
        }
        cpa_commit();
    };

    // prologue: async K/V tile 0, plain Q stage in parallel
    issueKV(0, 0);
    {
        const __nv_bfloat16* Qh_ = Qh + (size_t)bh * Ss * DEPTH;
        const __nv_bfloat16* Ql_ = Ql + (size_t)bh * Ss * DEPTH;
        #pragma unroll
        for (int i = 0; i < 4; i++) {
            int idx = tid + i * 256;
            int r = idx >> 3, sg = idx & 7;
            size_t go = (size_t)(m0 + r) * 64 + sg * 8;
            uint32_t off = (uint32_t)r * 128 + (((uint32_t)sg ^ (uint32_t)(r & 7)) << 4);
            *(uint4*)(smem + off)         = *(const uint4*)(Qh_ + go);
            *(uint4*)(smem + 16384 + off) = *(const uint4*)(Ql_ + go);
        }
    }
    if (tid < 128) SUM[tid] = 0.f;
    cpa_wait<0>();
    __syncthreads();

    float acc2[2][4][4] = {};   // ctx accumulator (unnormalized)

    for (int t = 0; t < 16; t++) {
        const int buf = t & 1;
        const int sk0 = t * 128;
        const uint32_t kbase = sb + F_K0 + buf * 32768;
        const uint32_t vbase = sb + F_V0 + buf * 32768;

        // QK tile
        float acc[4][4][4] = {};
        qk_tile_mma(sb, sb + 16384, kbase, kbase + 16384, lane, m0w, n0w, acc);

        // epilogue: e = exp(v) (no max), write unnormalized e, stash hi/lo, rowsum
        #pragma unroll
        for (int mi = 0; mi < 4; mi++)
            #pragma unroll
            for (int h = 0; h < 2; h++) {
                int rl = m0w + mi * 16 + (lane >> 2) + h * 8;
                int sq = m0 + rl;
                float rs = 0.f;
                #pragma unroll
                for (int nj = 0; nj < 4; nj++) {
                    int cl = n0w + nj * 8 + (lane & 3) * 2;
                    int sk = sk0 + cl;
                    float v0 = acc[mi][nj][h * 2] * 0.125f
                             + __ldg(mask + (size_t)sq * Ss + sk) * -1e9f;
                    float v1 = acc[mi][nj][h * 2 + 1] * 0.125f
                             + __ldg(mask + (size_t)sq * Ss + sk + 1) * -1e9f;
                    float e0 = __expf(v0), e1 = __expf(v1);
                    rs += e0 + e1;
                    *(float2*)(attn + ((size_t)bh * Ss + sq) * Ss + sk) = make_float2(e0, e1);
                    __nv_bfloat16 h0 = __float2bfloat16(e0);
                    __nv_bfloat16 h1 = __float2bfloat16(e1);
                    __nv_bfloat16 l0 = __float2bfloat16(e0 - __bfloat162float(h0));
                    __nv_bfloat16 l1 = __float2bfloat16(e1 - __bfloat162float(h1));
                    uint32_t off = (uint32_t)rl * 256
                                 + ((((uint32_t)cl >> 3) ^ (uint32_t)(rl & 7)) << 4)
                                 + ((uint32_t)cl & 7) * 2;
                    *(__nv_bfloat162*)(smem + F_PH + off) = __halves2bfloat162(h0, h1);
                    *(__nv_bfloat162*)(smem + F_PL + off) = __halves2bfloat162(l0, l1);
                }
                rs += __shfl_xor_sync(0xffffffffu, rs, 1);
                rs += __shfl_xor_sync(0xffffffffu, rs, 2);
                if ((lane & 3) == 0) RED[(wid & 3) * 128 + rl] = rs;
            }
        __syncthreads();
        if (tid < 128)
            SUM[tid] += RED[tid] + RED[128 + tid] + RED[256 + tid] + RED[384 + tid];

        // prefetch next K/V while PV computes
        if (t + 1 < 16) issueKV(t + 1, buf ^ 1);

        // PV tile: ctx += E(128x128) x V^T(64x128)
        #pragma unroll
        for (int ks = 0; ks < 8; ks++) {
            uint32_t pa_h[2][4], pa_l[2][4];
            #pragma unroll
            for (int mi = 0; mi < 2; mi++) {
                int r = m0w2 + mi * 16 + (lane & 15);
                uint32_t ch = (uint32_t)ks * 2 + (lane >> 4);
                uint32_t ad = (uint32_t)r * 256 + ((ch ^ (uint32_t)(r & 7)) << 4);
                ldsm_x4(pa_h[mi], sb + F_PH + ad);
                ldsm_x4(pa_l[mi], sb + F_PL + ad);
            }
            #pragma unroll
            for (int nbj = 0; nbj < 2; nbj++) {
                int n = n0w2 + nbj * 16 + ((lane >> 4) << 3) + (lane & 7);
                uint32_t ch = (uint32_t)ks * 2 + ((lane >> 3) & 1);
                uint32_t bd = (uint32_t)n * 256 + ((ch ^ (uint32_t)(n & 7)) << 4);
                uint32_t vh[4], vl[4];
                ldsm_x4(vh, vbase + bd);
                ldsm_x4(vl, vbase + 16384 + bd);
                #pragma unroll
                for (int mi = 0; mi < 2; mi++) {
                    mma16816(acc2[mi][nbj * 2],     pa_h[mi], vh);
                    mma16816(acc2[mi][nbj * 2 + 1], pa_h[mi], vh + 2);
                    mma16816(acc2[mi][nbj * 2],     pa_h[mi], vl);
                    mma16816(acc2[mi][nbj * 2 + 1], pa_h[mi], vl + 2);
                    mma16816(acc2[mi][nbj * 2],     pa_l[mi], vh);
                    mma16816(acc2[mi][nbj * 2 + 1], pa_l[mi], vh + 2);
                }
            }
        }
        cpa_wait<0>();
        __syncthreads();
    }

    // write inverse sums for the normalize pass
    if (tid < 128) invsum[(size_t)bh * Ss + m0 + tid] = 1.0f / SUM[tid];

    // ctx epilogue: scale by 1/rowsum -> bf16 hi/lo [b,s,1024]
    #pragma unroll
    for (int mi = 0; mi < 2; mi++)
        #pragma unroll
        for (int e = 0; e < 4; e += 2) {
            int rl = m0w2 + mi * 16 + (lane >> 2) + (e >> 1) * 8;
            float inv = 1.0f / SUM[rl];
            int s = m0 + rl;
            #pragma unroll
            for (int nj = 0; nj < 4; nj++)
                #pragma unroll
                for (int e2 = 0; e2 < 2; e2++) {
                    int d = n0w2 + nj * 8 + (lane & 3) * 2 + e2;
                    float v = acc2[mi][nj][e + e2] * inv;
                    __nv_bfloat16 hv = __float2bfloat16(v);
                    __nv_bfloat16 lv = __float2bfloat16(v - __bfloat162float(hv));
                    size_t idx = ((size_t)(b * Ss + s)) * Dd + hh * DEPTH + d;
                    Ch[idx] = hv; Cl[idx] = lv;
                }
        }
}

// ---------------- normalize attn in place: row *= inv[row] ----------------
__global__ void __launch_bounds__(256)
norm_kernel(float* __restrict__ attn, const float* __restrict__ inv)
{
    size_t row = blockIdx.x;
    float iv = __ldg(inv + row);
    float4* p = (float4*)(attn + row * Ss);
    int tid = threadIdx.x;
    #pragma unroll
    for (int i = 0; i < 2; i++) {
        float4 v = p[tid + i * 256];
        v.x *= iv; v.y *= iv; v.z *= iv; v.w *= iv;
        p[tid + i * 256] = v;
    }
}

// ---------------- W transpose + hi/lo split ----------------
__global__ void transpose_conv_kernel(const float* __restrict__ W,
                                      __nv_bfloat16* __restrict__ Th,
                                      __nv_bfloat16* __restrict__ Tl)
{
    __shared__ float t[32][33];
    int tx = threadIdx.x, ty = threadIdx.y;
    int x = blockIdx.x * 32 + tx;
    int y = blockIdx.y * 32 + ty;
    t[ty][tx] = W[(size_t)y * Dd + x];
    __syncthreads();
    int n = blockIdx.x * 32 + ty;
    int k = blockIdx.y * 32 + tx;
    float v = t[tx][ty];
    __nv_bfloat16 hv = __float2bfloat16(v);
    Th[(size_t)n * Dd + k] = hv;
    Tl[(size_t)n * Dd + k] = __float2bfloat16(v - __bfloat162float(hv));
}

// ---------------------------------------------------------------------------
extern "C" void kernel_launch(void* const* d_in, const int* in_sizes, int n_in,
                              void* d_out, int out_size) {
    const float* q    = (const float*)d_in[0];
    const float* k    = (const float*)d_in[1];
    const float* v    = (const float*)d_in[2];
    const float* mask = (const float*)d_in[3];
    const float* Wq   = (const float*)d_in[4];
    const float* bq   = (const float*)d_in[5];
    const float* Wk   = (const float*)d_in[6];
    const float* bk   = (const float*)d_in[7];
    const float* Wv   = (const float*)d_in[8];
    const float* bv   = (const float*)d_in[9];
    const float* Wo   = (const float*)d_in[10];
    const float* bo   = (const float*)d_in[11];
    float* out = (float*)d_out;

    const size_t OUT_ELEMS  = (size_t)BS * Dd;
    const size_t ATTN_ELEMS = (size_t)BH * Ss * Ss;

    float* attnbuf = nullptr;
    cudaGetSymbolAddress((void**)&attnbuf, g_attn);
    if ((size_t)out_size >= OUT_ELEMS + ATTN_ELEMS) attnbuf = out + OUT_ELEMS;

    __nv_bfloat16 *dWth, *dWtl, *dQh, *dQl, *dKh, *dKl, *dVth, *dVtl, *dCh, *dCl;
    float* dInv;
    cudaGetSymbolAddress((void**)&dWth, g_Wth);
    cudaGetSymbolAddress((void**)&dWtl, g_Wtl);
    cudaGetSymbolAddress((void**)&dQh,  g_Qh);
    cudaGetSymbolAddress((void**)&dQl,  g_Ql);
    cudaGetSymbolAddress((void**)&dKh,  g_Kh);
    cudaGetSymbolAddress((void**)&dKl,  g_Kl);
    cudaGetSymbolAddress((void**)&dVth, g_Vth);
    cudaGetSymbolAddress((void**)&dVtl, g_Vtl);
    cudaGetSymbolAddress((void**)&dCh,  g_Ch);
    cudaGetSymbolAddress((void**)&dCl,  g_Cl);
    cudaGetSymbolAddress((void**)&dInv, g_inv);

    cudaFuncSetAttribute(proj_kernel<0>,    cudaFuncAttributeMaxDynamicSharedMemorySize, SMEM_PROJ);
    cudaFuncSetAttribute(proj_kernel<1>,    cudaFuncAttributeMaxDynamicSharedMemorySize, SMEM_PROJ);
    cudaFuncSetAttribute(attn_fused_kernel, cudaFuncAttributeMaxDynamicSharedMemorySize, SMEM_FUSED);

    dim3 tposeBlk(32, 32), tposeGrid(32, 32);
    dim3 projGrid(8, 64);

    transpose_conv_kernel<<<tposeGrid, tposeBlk>>>(Wq, dWth, dWtl);
    proj_kernel<0><<<projGrid, 256, SMEM_PROJ>>>(q, nullptr, nullptr, dWth, dWtl,
                                                 bq, nullptr, dQh, dQl, 1);
    transpose_conv_kernel<<<tposeGrid, tposeBlk>>>(Wk, dWth, dWtl);
    proj_kernel<0><<<projGrid, 256, SMEM_PROJ>>>(k, nullptr, nullptr, dWth, dWtl,
                                                 bk, nullptr, dKh, dKl, 1);
    transpose_conv_kernel<<<tposeGrid, tposeBlk>>>(Wv, dWth, dWtl);
    proj_kernel<0><<<projGrid, 256, SMEM_PROJ>>>(v, nullptr, nullptr, dWth, dWtl,
                                                 bv, nullptr, dVth, dVtl, 2);

    attn_fused_kernel<<<dim3(16, 64), 256, SMEM_FUSED>>>(dQh, dQl, dKh, dKl, dVth, dVtl,
                                                         mask, attnbuf, dInv, dCh, dCl);
    norm_kernel<<<BH * Ss, 256>>>(attnbuf, dInv);

    transpose_conv_kernel<<<tposeGrid, tposeBlk>>>(Wo, dWth, dWtl);
    proj_kernel<1><<<projGrid, 256, SMEM_PROJ>>>(nullptr, dCh, dCl, dWth, dWtl,
                                                 bo, out, nullptr, nullptr, 0);
}

// round 11
// speedup vs baseline: 1.2237x; 1.0595x over previous
#include <cuda_runtime.h>
#include <cuda_bf16.h>
#include <cstdint>

#define Bb 4
#define Ss 2048
#define Dd 1024
#define Hh 16
#define DEPTH 64
#define BS (Bb * Ss)   // 8192
#define BH (Bb * Hh)   // 64

// ---------------- device scratch (allocation-free rule) ----------------
__device__ __nv_bfloat16 g_Wth[(size_t)4 * Dd * Dd];     // all 4 W^T hi
__device__ __nv_bfloat16 g_Wtl[(size_t)4 * Dd * Dd];     // all 4 W^T lo
__device__ __nv_bfloat16 g_Xh[(size_t)3 * BS * Dd];      // q,k,v activations hi
__device__ __nv_bfloat16 g_Xl[(size_t)3 * BS * Dd];      // q,k,v activations lo
__device__ __nv_bfloat16 g_Qh[(size_t)BH * Ss * DEPTH];  // [bh][s][64]
__device__ __nv_bfloat16 g_Ql[(size_t)BH * Ss * DEPTH];
__device__ __nv_bfloat16 g_Kh[(size_t)BH * Ss * DEPTH];
__device__ __nv_bfloat16 g_Kl[(size_t)BH * Ss * DEPTH];
__device__ __nv_bfloat16 g_Vth[(size_t)BH * DEPTH * Ss]; // V^T [bh][d][s]
__device__ __nv_bfloat16 g_Vtl[(size_t)BH * DEPTH * Ss];
__device__ __nv_bfloat16 g_Ch[(size_t)BS * Dd];          // ctx hi [b,s,1024]
__device__ __nv_bfloat16 g_Cl[(size_t)BS * Dd];
__device__ float g_inv[(size_t)BH * Ss];                 // 1/rowsum
__device__ float g_attn[(size_t)BH * Ss * Ss];           // fallback fp32 attn (1 GB)

// ---------------- PTX helpers ----------------
__device__ __forceinline__ uint32_t smem_u32(const void* p) {
    uint32_t a;
    asm("{ .reg .u64 t; cvta.to.shared.u64 t, %1; cvt.u32.u64 %0, t; }" : "=r"(a) : "l"(p));
    return a;
}
__device__ __forceinline__ void ldsm_x4(uint32_t* r, uint32_t addr) {
    asm volatile("ldmatrix.sync.aligned.m8n8.x4.shared.b16 {%0,%1,%2,%3}, [%4];"
                 : "=r"(r[0]), "=r"(r[1]), "=r"(r[2]), "=r"(r[3]) : "r"(addr));
}
__device__ __forceinline__ void mma16816(float* d, const uint32_t* a, const uint32_t* b) {
    asm volatile(
        "mma.sync.aligned.m16n8k16.row.col.f32.bf16.bf16.f32 "
        "{%0,%1,%2,%3}, {%4,%5,%6,%7}, {%8,%9}, {%0,%1,%2,%3};"
        : "+f"(d[0]), "+f"(d[1]), "+f"(d[2]), "+f"(d[3])
        : "r"(a[0]), "r"(a[1]), "r"(a[2]), "r"(a[3]), "r"(b[0]), "r"(b[1]));
}
__device__ __forceinline__ void cpa16(uint32_t dst, const void* src) {
    asm volatile("cp.async.cg.shared.global [%0], [%1], 16;" :: "r"(dst), "l"(src));
}
__device__ __forceinline__ void cpa_commit() {
    asm volatile("cp.async.commit_group;" ::: "memory");
}
template <int N>
__device__ __forceinline__ void cpa_wait() {
    asm volatile("cp.async.wait_group %0;" :: "n"(N) : "memory");
}

// ---------------- all-bf16 GEMM mainloop, cp.async A(single)+B(double) --------
// smem: A hi 0..16K, A lo 16K..32K, B buf0 32K (hi16K lo16K), B buf1 64K. 96K total.
__device__ __forceinline__ void gemm_core(
    const __nv_bfloat16* __restrict__ Ah, const __nv_bfloat16* __restrict__ Al, int lda,
    const __nv_bfloat16* __restrict__ Bh, const __nv_bfloat16* __restrict__ Bl, int ldb,
    int m0, int n0, int nChunks, char* smem,
    float (*acc)[4][4])
{
    constexpr int OFF_AL = 16384;
    constexpr int OFF_B  = 32768;
    constexpr int BSZ    = 32768;

    const int tid = threadIdx.x, wid = tid >> 5, lane = tid & 31;
    const int m0w = (wid >> 2) * 64, n0w = (wid & 3) * 32;
    const uint32_t sb = smem_u32(smem);

    auto issueB = [&](int c, int buf) {
        uint32_t base = sb + OFF_B + buf * BSZ;
        #pragma unroll
        for (int i = 0; i < 4; i++) {
            int idx = tid + i * 256;
            int r = idx >> 3, sg = idx & 7;
            size_t go = (size_t)(n0 + r) * ldb + c * 64 + sg * 8;
            uint32_t off = (uint32_t)r * 128 + (((uint32_t)sg * 16) ^ (((uint32_t)(r & 7)) << 4));
            cpa16(base + off,         Bh + go);
            cpa16(base + 16384 + off, Bl + go);
        }
        cpa_commit();
    };
    auto issueA = [&](int c) {
        #pragma unroll
        for (int i = 0; i < 4; i++) {
            int idx = tid + i * 256;
            int r = idx >> 3, sg = idx & 7;
            size_t go = (size_t)(m0 + r) * lda + c * 64 + sg * 8;
            uint32_t off = (uint32_t)r * 128 + (((uint32_t)sg * 16) ^ (((uint32_t)(r & 7)) << 4));
            cpa16(sb + off,          Ah + go);
            cpa16(sb + OFF_AL + off, Al + go);
        }
        cpa_commit();
    };

    issueB(0, 0);

    for (int c = 0; c < nChunks; c++) {
        const int buf = c & 1;
        __syncthreads();                 // prior compute done; A buffer free
        issueA(c);
        if (c + 1 < nChunks) { issueB(c + 1, buf ^ 1); cpa_wait<1>(); }
        else                 { cpa_wait<0>(); }
        __syncthreads();

        const uint32_t bbase = sb + OFF_B + buf * BSZ;
        #pragma unroll
        for (int ks = 0; ks < 4; ks++) {
            uint32_t ah[4][4], al[4][4];
            #pragma unroll
            for (int mi = 0; mi < 4; mi++) {
                int r = m0w + mi * 16 + (lane & 15);
                uint32_t kb = (uint32_t)ks * 32 + (((uint32_t)(lane >> 4)) << 4);
                uint32_t ad = sb + (uint32_t)r * 128 + (kb ^ (((uint32_t)(r & 7)) << 4));
                ldsm_x4(ah[mi], ad);
                ldsm_x4(al[mi], ad + OFF_AL);
            }
            #pragma unroll
            for (int nb = 0; nb < 2; nb++) {
                int n = n0w + nb * 16 + ((lane >> 4) << 3) + (lane & 7);
                uint32_t kb = (uint32_t)ks * 32 + (((uint32_t)((lane >> 3) & 1)) << 4);
                uint32_t bd = bbase + (uint32_t)n * 128 + (kb ^ (((uint32_t)(n & 7)) << 4));
                uint32_t bh[4], bl[4];
                ldsm_x4(bh, bd);
                ldsm_x4(bl, bd + 16384);
                #pragma unroll
                for (int mi = 0; mi < 4; mi++) {
                    mma16816(acc[mi][nb * 2],     ah[mi], bh);
                    mma16816(acc[mi][nb * 2 + 1], ah[mi], bh + 2);
                    mma16816(acc[mi][nb * 2],     ah[mi], bl);
                    mma16816(acc[mi][nb * 2 + 1], ah[mi], bl + 2);
                    mma16816(acc[mi][nb * 2],     al[mi], bh);
                    mma16816(acc[mi][nb * 2 + 1], al[mi], bh + 2);
                }
            }
        }
    }
}

static constexpr int SMEM_PROJ = 98304;  // A 32K + B double 64K

// ---------------- Q/K/V projection GEMM ----------------
// mode 1: bf16 hi/lo head layout [bh][s][64]; mode 2: bf16 hi/lo V^T [bh][d][s].
__global__ void __launch_bounds__(256, 2)
proj_kernel(const __nv_bfloat16* __restrict__ Ah, const __nv_bfloat16* __restrict__ Al,
            const __nv_bfloat16* __restrict__ Bh, const __nv_bfloat16* __restrict__ Bl,
            const float* __restrict__ bias,
            __nv_bfloat16* __restrict__ oH, __nv_bfloat16* __restrict__ oL, int mode)
{
    extern __shared__ char smem[];
    int m0 = blockIdx.y * 128, n0 = blockIdx.x * 128;
    float acc[4][4][4] = {};
    gemm_core(Ah, Al, 1024, Bh, Bl, 1024, m0, n0, 16, smem, acc);

    int tid = threadIdx.x, wid = tid >> 5, lane = tid & 31;
    int m0w = (wid >> 2) * 64, n0w = (wid & 3) * 32;
    #pragma unroll
    for (int mi = 0; mi < 4; mi++)
        #pragma unroll
        for (int nj = 0; nj < 4; nj++)
            #pragma unroll
            for (int e = 0; e < 4; e++) {
                int r  = m0 + m0w + mi * 16 + (lane >> 2) + (e >> 1) * 8;
                int cc = n0 + n0w + nj * 8 + (lane & 3) * 2 + (e & 1);
                float v = acc[mi][nj][e] + __ldg(bias + cc);
                __nv_bfloat16 hv = __float2bfloat16(v);
                __nv_bfloat16 lv = __float2bfloat16(v - __bfloat162float(hv));
                int b = r >> 11, s = r & 2047, h = cc >> 6, d = cc & 63;
                size_t bh = (size_t)(b * Hh + h);
                size_t idx = (mode == 1) ? ((bh * Ss + s) << 6) + d
                                         : (bh * DEPTH + d) * Ss + s;
                oH[idx] = hv; oL[idx] = lv;
            }
}

// ---------------- fat output kernel: proj-out (blocks 0..511) + attn norm ----
__global__ void __launch_bounds__(256, 2)
fat_out_kernel(const __nv_bfloat16* __restrict__ Ah, const __nv_bfloat16* __restrict__ Al,
               const __nv_bfloat16* __restrict__ Bh, const __nv_bfloat16* __restrict__ Bl,
               const float* __restrict__ bias, float* __restrict__ outF,
               float* __restrict__ attn, const float* __restrict__ inv)
{
    if (blockIdx.x < 512) {
        extern __shared__ char smem[];
        int m0 = (blockIdx.x >> 3) * 128, n0 = (blockIdx.x & 7) * 128;
        float acc[4][4][4] = {};
        gemm_core(Ah, Al, 1024, Bh, Bl, 1024, m0, n0, 16, smem, acc);

        int tid = threadIdx.x, wid = tid >> 5, lane = tid & 31;
        int m0w = (wid >> 2) * 64, n0w = (wid & 3) * 32;
        #pragma unroll
        for (int mi = 0; mi < 4; mi++)
            #pragma unroll
            for (int nj = 0; nj < 4; nj++)
                #pragma unroll
                for (int e = 0; e < 4; e++) {
                    int r  = m0 + m0w + mi * 16 + (lane >> 2) + (e >> 1) * 8;
                    int cc = n0 + n0w + nj * 8 + (lane & 3) * 2 + (e & 1);
                    outF[(size_t)r * Dd + cc] = acc[mi][nj][e] + __ldg(bias + cc);
                }
    } else {
        // norm: 4 rows per block, 8 batched ld.128 per thread for MLP
        int nb = blockIdx.x - 512;            // 0..32767
        size_t row0 = (size_t)nb * 4;
        int tid = threadIdx.x;
        float4* p = (float4*)attn + row0 * (Ss / 4);
        float4 vb[8];
        #pragma unroll
        for (int j = 0; j < 8; j++) vb[j] = p[tid + j * 256];
        #pragma unroll
        for (int j = 0; j < 8; j++) {
            float iv = __ldg(inv + row0 + ((unsigned)(tid + j * 256) >> 9));
            vb[j].x *= iv; vb[j].y *= iv; vb[j].z *= iv; vb[j].w *= iv;
            p[tid + j * 256] = vb[j];
        }
    }
}

// ============ fused attention (single QK pass, max-free softmax) ============
static constexpr int F_K0  = 32768;
static constexpr int F_V0  = 98304;
static constexpr int F_PH  = 163840;
static constexpr int F_PL  = 196608;
static constexpr int F_RED = 229376;
static constexpr int F_SUM = 231424;
static constexpr int SMEM_FUSED = 231936;

__device__ __forceinline__ void qk_tile_mma(
    uint32_t sb_qh, uint32_t sb_ql, uint32_t sb_kh, uint32_t sb_kl,
    int lane, int m0w, int n0w, float acc[4][4][4])
{
    #pragma unroll
    for (int ks = 0; ks < 4; ks++) {
        uint32_t ah[4][4], al[4][4];
        #pragma unroll
        for (int mi = 0; mi < 4; mi++) {
            int r = m0w + mi * 16 + (lane & 15);
            uint32_t ch = (uint32_t)ks * 2 + (lane >> 4);
            uint32_t ad = (uint32_t)r * 128 + ((ch ^ (uint32_t)(r & 7)) << 4);
            ldsm_x4(ah[mi], sb_qh + ad);
            ldsm_x4(al[mi], sb_ql + ad);
        }
        #pragma unroll
        for (int nb = 0; nb < 2; nb++) {
            int n = n0w + nb * 16 + ((lane >> 4) << 3) + (lane & 7);
            uint32_t ch = (uint32_t)ks * 2 + ((lane >> 3) & 1);
            uint32_t bd = (uint32_t)n * 128 + ((ch ^ (uint32_t)(n & 7)) << 4);
            uint32_t bh[4], bl[4];
            ldsm_x4(bh, sb_kh + bd);
            ldsm_x4(bl, sb_kl + bd);
            #pragma unroll
            for (int mi = 0; mi < 4; mi++) {
                mma16816(acc[mi][nb * 2],     ah[mi], bh);
                mma16816(acc[mi][nb * 2 + 1], ah[mi], bh + 2);
                mma16816(acc[mi][nb * 2],     ah[mi], bl);
                mma16816(acc[mi][nb * 2 + 1], ah[mi], bl + 2);
                mma16816(acc[mi][nb * 2],     al[mi], bh);
                mma16816(acc[mi][nb * 2 + 1], al[mi], bh + 2);
            }
        }
    }
}

__global__ void __launch_bounds__(256)
attn_fused_kernel(const __nv_bfloat16* __restrict__ Qh, const __nv_bfloat16* __restrict__ Ql,
                  const __nv_bfloat16* __restrict__ Kh, const __nv_bfloat16* __restrict__ Kl,
                  const __nv_bfloat16* __restrict__ Vth, const __nv_bfloat16* __restrict__ Vtl,
                  const float* __restrict__ mask,
                  float* __restrict__ attn, float* __restrict__ invsum,
                  __nv_bfloat16* __restrict__ Ch, __nv_bfloat16* __restrict__ Cl)
{
    extern __shared__ char smem[];
    const uint32_t sb = smem_u32(smem);
    const int tid = threadIdx.x, wid = tid >> 5, lane = tid & 31;
    const int m0w = (wid >> 2) * 64, n0w = (wid & 3) * 32;
    const int m0w2 = (wid >> 1) * 32, n0w2 = (wid & 1) * 32;
    const int bh = blockIdx.y, m0 = blockIdx.x * 128;
    const int b = bh >> 4, hh = bh & 15;
    const __nv_bfloat16* Kh_ = Kh + (size_t)bh * Ss * DEPTH;
    const __nv_bfloat16* Kl_ = Kl + (size_t)bh * Ss * DEPTH;
    const __nv_bfloat16* Vh_ = Vth + (size_t)bh * DEPTH * Ss;
    const __nv_bfloat16* Vl_ = Vtl + (size_t)bh * DEPTH * Ss;
    float* RED = (float*)(smem + F_RED);
    float* SUM = (float*)(smem + F_SUM);

    auto issueKV = [&](int t1, int buf) {
        const int sk0n = t1 * 128;
        uint32_t kb = sb + F_K0 + buf * 32768;
        uint32_t vbp = sb + F_V0 + buf * 32768;
        #pragma unroll
        for (int i = 0; i < 4; i++) {
            int idx = tid + i * 256;
            int r = idx >> 3, sg = idx & 7;
            size_t go = (size_t)(sk0n + r) * 64 + sg * 8;
            uint32_t off = (uint32_t)r * 128 + (((uint32_t)sg ^ (uint32_t)(r & 7)) << 4);
            cpa16(kb + off,         Kh_ + go);
            cpa16(kb + 16384 + off, Kl_ + go);
        }
        #pragma unroll
        for (int i = 0; i < 4; i++) {
            int idx = tid + i * 256;
            int d = idx >> 4, ch = idx & 15;
            size_t go = (size_t)d * Ss + sk0n + ch * 8;
            uint32_t off = (uint32_t)d * 256 + (((uint32_t)ch ^ (uint32_t)(d & 7)) << 4);
            cpa16(vbp + off,         Vh_ + go);
            cpa16(vbp + 16384 + off, Vl_ + go);
        }
        cpa_commit();
    };

    issueKV(0, 0);
    {
        const __nv_bfloat16* Qh_ = Qh + (size_t)bh * Ss * DEPTH;
        const __nv_bfloat16* Ql_ = Ql + (size_t)bh * Ss * DEPTH;
        #pragma unroll
        for (int i = 0; i < 4; i++) {
            int idx = tid + i * 256;
            int r = idx >> 3, sg = idx & 7;
            size_t go = (size_t)(m0 + r) * 64 + sg * 8;
            uint32_t off = (uint32_t)r * 128 + (((uint32_t)sg ^ (uint32_t)(r & 7)) << 4);
            *(uint4*)(smem + off)         = *(const uint4*)(Qh_ + go);
            *(uint4*)(smem + 16384 + off) = *(const uint4*)(Ql_ + go);
        }
    }
    if (tid < 128) SUM[tid] = 0.f;
    cpa_wait<0>();
    __syncthreads();

    float acc2[2][4][4] = {};

    for (int t = 0; t < 16; t++) {
        const int buf = t & 1;
        const int sk0 = t * 128;
        const uint32_t kbase = sb + F_K0 + buf * 32768;
        const uint32_t vbase = sb + F_V0 + buf * 32768;

        float acc[4][4][4] = {};
        qk_tile_mma(sb, sb + 16384, kbase, kbase + 16384, lane, m0w, n0w, acc);

        #pragma unroll
        for (int mi = 0; mi < 4; mi++)
            #pragma unroll
            for (int h = 0; h < 2; h++) {
                int rl = m0w + mi * 16 + (lane >> 2) + h * 8;
                int sq = m0 + rl;
                float rs = 0.f;
                #pragma unroll
                for (int nj = 0; nj < 4; nj++) {
                    int cl = n0w + nj * 8 + (lane & 3) * 2;
                    int sk = sk0 + cl;
                    float v0 = acc[mi][nj][h * 2] * 0.125f
                             + __ldg(mask + (size_t)sq * Ss + sk) * -1e9f;
                    float v1 = acc[mi][nj][h * 2 + 1] * 0.125f
                             + __ldg(mask + (size_t)sq * Ss + sk + 1) * -1e9f;
                    float e0 = __expf(v0), e1 = __expf(v1);
                    rs += e0 + e1;
                    *(float2*)(attn + ((size_t)bh * Ss + sq) * Ss + sk) = make_float2(e0, e1);
                    __nv_bfloat16 h0 = __float2bfloat16(e0);
                    __nv_bfloat16 h1 = __float2bfloat16(e1);
                    __nv_bfloat16 l0 = __float2bfloat16(e0 - __bfloat162float(h0));
                    __nv_bfloat16 l1 = __float2bfloat16(e1 - __bfloat162float(h1));
                    uint32_t off = (uint32_t)rl * 256
                                 + ((((uint32_t)cl >> 3) ^ (uint32_t)(rl & 7)) << 4)
                                 + ((uint32_t)cl & 7) * 2;
                    *(__nv_bfloat162*)(smem + F_PH + off) = __halves2bfloat162(h0, h1);
                    *(__nv_bfloat162*)(smem + F_PL + off) = __halves2bfloat162(l0, l1);
                }
                rs += __shfl_xor_sync(0xffffffffu, rs, 1);
                rs += __shfl_xor_sync(0xffffffffu, rs, 2);
                if ((lane & 3) == 0) RED[(wid & 3) * 128 + rl] = rs;
            }
        __syncthreads();
        if (tid < 128)
            SUM[tid] += RED[tid] + RED[128 + tid] + RED[256 + tid] + RED[384 + tid];

        if (t + 1 < 16) issueKV(t + 1, buf ^ 1);

        #pragma unroll
        for (int ks = 0; ks < 8; ks++) {
            uint32_t pa_h[2][4], pa_l[2][4];
            #pragma unroll
            for (int mi = 0; mi < 2; mi++) {
                int r = m0w2 + mi * 16 + (lane & 15);
                uint32_t ch = (uint32_t)ks * 2 + (lane >> 4);
                uint32_t ad = (uint32_t)r * 256 + ((ch ^ (uint32_t)(r & 7)) << 4);
                ldsm_x4(pa_h[mi], sb + F_PH + ad);
                ldsm_x4(pa_l[mi], sb + F_PL + ad);
            }
            #pragma unroll
            for (int nbj = 0; nbj < 2; nbj++) {
                int n = n0w2 + nbj * 16 + ((lane >> 4) << 3) + (lane & 7);
                uint32_t ch = (uint32_t)ks * 2 + ((lane >> 3) & 1);
                uint32_t bd = (uint32_t)n * 256 + ((ch ^ (uint32_t)(n & 7)) << 4);
                uint32_t vh[4], vl[4];
                ldsm_x4(vh, vbase + bd);
                ldsm_x4(vl, vbase + 16384 + bd);
                #pragma unroll
                for (int mi = 0; mi < 2; mi++) {
                    mma16816(acc2[mi][nbj * 2],     pa_h[mi], vh);
                    mma16816(acc2[mi][nbj * 2 + 1], pa_h[mi], vh + 2);
                    mma16816(acc2[mi][nbj * 2],     pa_h[mi], vl);
                    mma16816(acc2[mi][nbj * 2 + 1], pa_h[mi], vl + 2);
                    mma16816(acc2[mi][nbj * 2],     pa_l[mi], vh);
                    mma16816(acc2[mi][nbj * 2 + 1], pa_l[mi], vh + 2);
                }
            }
        }
        cpa_wait<0>();
        __syncthreads();
    }

    if (tid < 128) invsum[(size_t)bh * Ss + m0 + tid] = 1.0f / SUM[tid];

    #pragma unroll
    for (int mi = 0; mi < 2; mi++)
        #pragma unroll
        for (int e = 0; e < 4; e += 2) {
            int rl = m0w2 + mi * 16 + (lane >> 2) + (e >> 1) * 8;
            float inv = 1.0f / SUM[rl];
            int s = m0 + rl;
            #pragma unroll
            for (int nj = 0; nj < 4; nj++)
                #pragma unroll
                for (int e2 = 0; e2 < 2; e2++) {
                    int d = n0w2 + nj * 8 + (lane & 3) * 2 + e2;
                    float v = acc2[mi][nj][e + e2] * inv;
                    __nv_bfloat16 hv = __float2bfloat16(v);
                    __nv_bfloat16 lv = __float2bfloat16(v - __bfloat162float(hv));
                    size_t idx = ((size_t)(b * Ss + s)) * Dd + hh * DEPTH + d;
                    Ch[idx] = hv; Cl[idx] = lv;
                }
        }
}

// ---------------- fat prep: 4 W transposes + 3 activation hi/lo splits ------
__global__ void __launch_bounds__(1024)
prep_kernel(const float* __restrict__ Wq, const float* __restrict__ Wk,
            const float* __restrict__ Wv, const float* __restrict__ Wo,
            const float* __restrict__ q, const float* __restrict__ k,
            const float* __restrict__ v,
            __nv_bfloat16* __restrict__ Wth, __nv_bfloat16* __restrict__ Wtl,
            __nv_bfloat16* __restrict__ Xh,  __nv_bfloat16* __restrict__ Xl)
{
    int bid = blockIdx.x, tid = threadIdx.x;
    if (bid < 4096) {
        __shared__ float t[32][33];
        int w = bid >> 10, idx = bid & 1023;
        int bx = idx & 31, by = idx >> 5;
        const float* W = (w == 0) ? Wq : (w == 1) ? Wk : (w == 2) ? Wv : Wo;
        int tx = tid & 31, ty = tid >> 5;
        t[ty][tx] = W[(size_t)(by * 32 + ty) * Dd + bx * 32 + tx];
        __syncthreads();
        int n = bx * 32 + ty, kk = by * 32 + tx;
        float val = t[tx][ty];
        __nv_bfloat16 hv = __float2bfloat16(val);
        size_t o = (size_t)w * Dd * Dd + (size_t)n * Dd + kk;
        Wth[o] = hv;
        Wtl[o] = __float2bfloat16(val - __bfloat162float(hv));
    } else {
        int i = bid - 4096;
        int tsel = i >> 10, blk = i & 1023;
        const float* X = (tsel == 0) ? q : (tsel == 1) ? k : v;
        size_t base = (size_t)blk * 8192;
        #pragma unroll
        for (int j = 0; j < 2; j++) {
            size_t e = base + ((size_t)tid + j * 1024) * 4;
            float4 f = *(const float4*)(X + e);
            __align__(8) __nv_bfloat16 hb[4], lb[4];
            hb[0] = __float2bfloat16(f.x); lb[0] = __float2bfloat16(f.x - __bfloat162float(hb[0]));
            hb[1] = __float2bfloat16(f.y); lb[1] = __float2bfloat16(f.y - __bfloat162float(hb[1]));
            hb[2] = __float2bfloat16(f.z); lb[2] = __float2bfloat16(f.z - __bfloat162float(hb[2]));
            hb[3] = __float2bfloat16(f.w); lb[3] = __float2bfloat16(f.w - __bfloat162float(hb[3]));
            size_t oo = (size_t)tsel * BS * Dd + e;
            *(uint2*)(Xh + oo) = *(uint2*)hb;
            *(uint2*)(Xl + oo) = *(uint2*)lb;
        }
    }
}

// ---------------------------------------------------------------------------
extern "C" void kernel_launch(void* const* d_in, const int* in_sizes, int n_in,
                              void* d_out, int out_size) {
    const float* q    = (const float*)d_in[0];
    const float* k    = (const float*)d_in[1];
    const float* v    = (const float*)d_in[2];
    const float* mask = (const float*)d_in[3];
    const float* Wq   = (const float*)d_in[4];
    const float* bq   = (const float*)d_in[5];
    const float* Wk   = (const float*)d_in[6];
    const float* bk   = (const float*)d_in[7];
    const float* Wv   = (const float*)d_in[8];
    const float* bv   = (const float*)d_in[9];
    const float* Wo   = (const float*)d_in[10];
    const float* bo   = (const float*)d_in[11];
    float* out = (float*)d_out;

    const size_t OUT_ELEMS  = (size_t)BS * Dd;
    const size_t ATTN_ELEMS = (size_t)BH * Ss * Ss;

    float* attnbuf = nullptr;
    cudaGetSymbolAddress((void**)&attnbuf, g_attn);
    if ((size_t)out_size >= OUT_ELEMS + ATTN_ELEMS) attnbuf = out + OUT_ELEMS;

    __nv_bfloat16 *dWth, *dWtl, *dXh, *dXl;
    __nv_bfloat16 *dQh, *dQl, *dKh, *dKl, *dVth, *dVtl, *dCh, *dCl;
    float* dInv;
    cudaGetSymbolAddress((void**)&dWth, g_Wth);
    cudaGetSymbolAddress((void**)&dWtl, g_Wtl);
    cudaGetSymbolAddress((void**)&dXh,  g_Xh);
    cudaGetSymbolAddress((void**)&dXl,  g_Xl);
    cudaGetSymbolAddress((void**)&dQh,  g_Qh);
    cudaGetSymbolAddress((void**)&dQl,  g_Ql);
    cudaGetSymbolAddress((void**)&dKh,  g_Kh);
    cudaGetSymbolAddress((void**)&dKl,  g_Kl);
    cudaGetSymbolAddress((void**)&dVth, g_Vth);
    cudaGetSymbolAddress((void**)&dVtl, g_Vtl);
    cudaGetSymbolAddress((void**)&dCh,  g_Ch);
    cudaGetSymbolAddress((void**)&dCl,  g_Cl);
    cudaGetSymbolAddress((void**)&dInv, g_inv);

    cudaFuncSetAttribute(proj_kernel,       cudaFuncAttributeMaxDynamicSharedMemorySize, SMEM_PROJ);
    cudaFuncSetAttribute(fat_out_kernel,    cudaFuncAttributeMaxDynamicSharedMemorySize, SMEM_PROJ);
    cudaFuncSetAttribute(attn_fused_kernel, cudaFuncAttributeMaxDynamicSharedMemorySize, SMEM_FUSED);

    const size_t WSZ = (size_t)Dd * Dd;
    const size_t XSZ = (size_t)BS * Dd;
    dim3 projGrid(8, 64);

    // one fat prep: all transposes + all activation splits
    prep_kernel<<<7168, 1024>>>(Wq, Wk, Wv, Wo, q, k, v, dWth, dWtl, dXh, dXl);

    proj_kernel<<<projGrid, 256, SMEM_PROJ>>>(dXh,           dXl,           dWth,           dWtl,
                                              bq, dQh, dQl, 1);
    proj_kernel<<<projGrid, 256, SMEM_PROJ>>>(dXh + XSZ,     dXl + XSZ,     dWth + WSZ,     dWtl + WSZ,
                                              bk, dKh, dKl, 1);
    proj_kernel<<<projGrid, 256, SMEM_PROJ>>>(dXh + 2 * XSZ, dXl + 2 * XSZ, dWth + 2 * WSZ, dWtl + 2 * WSZ,
                                              bv, dVth, dVtl, 2);

    attn_fused_kernel<<<dim3(16, 64), 256, SMEM_FUSED>>>(dQh, dQl, dKh, dKl, dVth, dVtl,
                                                         mask, attnbuf, dInv, dCh, dCl);

    // fused: output projection (blocks 0..511) + attn normalization (rest)
    fat_out_kernel<<<512 + 32768, 256, SMEM_PROJ>>>(dCh, dCl, dWth + 3 * WSZ, dWtl + 3 * WSZ,
                                                    bo, out, attnbuf, dInv);
}

// round 14
// speedup vs baseline: 1.3057x; 1.0670x over previous
#include <cuda_runtime.h>
#include <cuda_bf16.h>
#include <cstdint>

#define Bb 4
#define Ss 2048
#define Dd 1024
#define Hh 16
#define DEPTH 64
#define BS (Bb * Ss)   // 8192
#define BH (Bb * Hh)   // 64

// ---------------- device scratch (allocation-free rule) ----------------
__device__ __nv_bfloat16 g_Wth[(size_t)4 * Dd * Dd];     // all 4 W^T hi
__device__ __nv_bfloat16 g_Wtl[(size_t)4 * Dd * Dd];     // all 4 W^T lo
__device__ __nv_bfloat16 g_Xh[(size_t)3 * BS * Dd];      // q,k,v activations hi
__device__ __nv_bfloat16 g_Xl[(size_t)3 * BS * Dd];      // q,k,v activations lo
__device__ __nv_bfloat16 g_Qh[(size_t)BH * Ss * DEPTH];  // [bh][s][64]
__device__ __nv_bfloat16 g_Ql[(size_t)BH * Ss * DEPTH];
__device__ __nv_bfloat16 g_Kh[(size_t)BH * Ss * DEPTH];
__device__ __nv_bfloat16 g_Kl[(size_t)BH * Ss * DEPTH];
__device__ __nv_bfloat16 g_Vth[(size_t)BH * DEPTH * Ss]; // V^T [bh][d][s]
__device__ __nv_bfloat16 g_Vtl[(size_t)BH * DEPTH * Ss];
__device__ __nv_bfloat16 g_Ch[(size_t)BS * Dd];          // ctx hi [b,s,1024]
__device__ __nv_bfloat16 g_Cl[(size_t)BS * Dd];
__device__ float g_inv[(size_t)BH * Ss];                 // 1/rowsum
__device__ float g_attn[(size_t)BH * Ss * Ss];           // fallback fp32 attn (1 GB)

// ---------------- PTX helpers ----------------
__device__ __forceinline__ uint32_t smem_u32(const void* p) {
    uint32_t a;
    asm("{ .reg .u64 t; cvta.to.shared.u64 t, %1; cvt.u32.u64 %0, t; }" : "=r"(a) : "l"(p));
    return a;
}
__device__ __forceinline__ void ldsm_x4(uint32_t* r, uint32_t addr) {
    asm volatile("ldmatrix.sync.aligned.m8n8.x4.shared.b16 {%0,%1,%2,%3}, [%4];"
                 : "=r"(r[0]), "=r"(r[1]), "=r"(r[2]), "=r"(r[3]) : "r"(addr));
}
__device__ __forceinline__ void mma16816(float* d, const uint32_t* a, const uint32_t* b) {
    asm volatile(
        "mma.sync.aligned.m16n8k16.row.col.f32.bf16.bf16.f32 "
        "{%0,%1,%2,%3}, {%4,%5,%6,%7}, {%8,%9}, {%0,%1,%2,%3};"
        : "+f"(d[0]), "+f"(d[1]), "+f"(d[2]), "+f"(d[3])
        : "r"(a[0]), "r"(a[1]), "r"(a[2]), "r"(a[3]), "r"(b[0]), "r"(b[1]));
}
__device__ __forceinline__ void cpa16(uint32_t dst, const void* src) {
    asm volatile("cp.async.cg.shared.global [%0], [%1], 16;" :: "r"(dst), "l"(src));
}
__device__ __forceinline__ void cpa_commit() {
    asm volatile("cp.async.commit_group;" ::: "memory");
}
template <int N>
__device__ __forceinline__ void cpa_wait() {
    asm volatile("cp.async.wait_group %0;" :: "n"(N) : "memory");
}

// ---------------- all-bf16 GEMM mainloop, cp.async A(single)+B(double) --------
__device__ __forceinline__ void gemm_core(
    const __nv_bfloat16* __restrict__ Ah, const __nv_bfloat16* __restrict__ Al, int lda,
    const __nv_bfloat16* __restrict__ Bh, const __nv_bfloat16* __restrict__ Bl, int ldb,
    int m0, int n0, int nChunks, char* smem,
    float (*acc)[4][4])
{
    constexpr int OFF_AL = 16384;
    constexpr int OFF_B  = 32768;
    constexpr int BSZ    = 32768;

    const int tid = threadIdx.x, wid = tid >> 5, lane = tid & 31;
    const int m0w = (wid >> 2) * 64, n0w = (wid & 3) * 32;
    const uint32_t sb = smem_u32(smem);

    auto issueB = [&](int c, int buf) {
        uint32_t base = sb + OFF_B + buf * BSZ;
        #pragma unroll
        for (int i = 0; i < 4; i++) {
            int idx = tid + i * 256;
            int r = idx >> 3, sg = idx & 7;
            size_t go = (size_t)(n0 + r) * ldb + c * 64 + sg * 8;
            uint32_t off = (uint32_t)r * 128 + (((uint32_t)sg * 16) ^ (((uint32_t)(r & 7)) << 4));
            cpa16(base + off,         Bh + go);
            cpa16(base + 16384 + off, Bl + go);
        }
        cpa_commit();
    };
    auto issueA = [&](int c) {
        #pragma unroll
        for (int i = 0; i < 4; i++) {
            int idx = tid + i * 256;
            int r = idx >> 3, sg = idx & 7;
            size_t go = (size_t)(m0 + r) * lda + c * 64 + sg * 8;
            uint32_t off = (uint32_t)r * 128 + (((uint32_t)sg * 16) ^ (((uint32_t)(r & 7)) << 4));
            cpa16(sb + off,          Ah + go);
            cpa16(sb + OFF_AL + off, Al + go);
        }
        cpa_commit();
    };

    issueB(0, 0);

    for (int c = 0; c < nChunks; c++) {
        const int buf = c & 1;
        __syncthreads();
        issueA(c);
        if (c + 1 < nChunks) { issueB(c + 1, buf ^ 1); cpa_wait<1>(); }
        else                 { cpa_wait<0>(); }
        __syncthreads();

        const uint32_t bbase = sb + OFF_B + buf * BSZ;
        #pragma unroll
        for (int ks = 0; ks < 4; ks++) {
            uint32_t ah[4][4], al[4][4];
            #pragma unroll
            for (int mi = 0; mi < 4; mi++) {
                int r = m0w + mi * 16 + (lane & 15);
                uint32_t kb = (uint32_t)ks * 32 + (((uint32_t)(lane >> 4)) << 4);
                uint32_t ad = sb + (uint32_t)r * 128 + (kb ^ (((uint32_t)(r & 7)) << 4));
                ldsm_x4(ah[mi], ad);
                ldsm_x4(al[mi], ad + OFF_AL);
            }
            #pragma unroll
            for (int nb = 0; nb < 2; nb++) {
                int n = n0w + nb * 16 + ((lane >> 4) << 3) + (lane & 7);
                uint32_t kb = (uint32_t)ks * 32 + (((uint32_t)((lane >> 3) & 1)) << 4);
                uint32_t bd = bbase + (uint32_t)n * 128 + (kb ^ (((uint32_t)(n & 7)) << 4));
                uint32_t bh[4], bl[4];
                ldsm_x4(bh, bd);
                ldsm_x4(bl, bd + 16384);
                #pragma unroll
                for (int mi = 0; mi < 4; mi++) {
                    mma16816(acc[mi][nb * 2],     ah[mi], bh);
                    mma16816(acc[mi][nb * 2 + 1], ah[mi], bh + 2);
                    mma16816(acc[mi][nb * 2],     ah[mi], bl);
                    mma16816(acc[mi][nb * 2 + 1], ah[mi], bl + 2);
                    mma16816(acc[mi][nb * 2],     al[mi], bh);
                    mma16816(acc[mi][nb * 2 + 1], al[mi], bh + 2);
                }
            }
        }
    }
}

static constexpr int SMEM_PROJ = 98304;

// ---------------- Q/K/V projection GEMM ----------------
__global__ void __launch_bounds__(256, 2)
proj_kernel(const __nv_bfloat16* __restrict__ Ah, const __nv_bfloat16* __restrict__ Al,
            const __nv_bfloat16* __restrict__ Bh, const __nv_bfloat16* __restrict__ Bl,
            const float* __restrict__ bias,
            __nv_bfloat16* __restrict__ oH, __nv_bfloat16* __restrict__ oL, int mode)
{
    extern __shared__ char smem[];
    int m0 = blockIdx.y * 128, n0 = blockIdx.x * 128;
    float acc[4][4][4] = {};
    gemm_core(Ah, Al, 1024, Bh, Bl, 1024, m0, n0, 16, smem, acc);

    int tid = threadIdx.x, wid = tid >> 5, lane = tid & 31;
    int m0w = (wid >> 2) * 64, n0w = (wid & 3) * 32;
    #pragma unroll
    for (int mi = 0; mi < 4; mi++)
        #pragma unroll
        for (int nj = 0; nj < 4; nj++)
            #pragma unroll
            for (int e = 0; e < 4; e++) {
                int r  = m0 + m0w + mi * 16 + (lane >> 2) + (e >> 1) * 8;
                int cc = n0 + n0w + nj * 8 + (lane & 3) * 2 + (e & 1);
                float v = acc[mi][nj][e] + __ldg(bias + cc);
                __nv_bfloat16 hv = __float2bfloat16(v);
                __nv_bfloat16 lv = __float2bfloat16(v - __bfloat162float(hv));
                int b = r >> 11, s = r & 2047, h = cc >> 6, d = cc & 63;
                size_t bh = (size_t)(b * Hh + h);
                size_t idx = (mode == 1) ? ((bh * Ss + s) << 6) + d
                                         : (bh * DEPTH + d) * Ss + s;
                oH[idx] = hv; oL[idx] = lv;
            }
}

// ---------------- fat output kernel: proj-out + attn norm ----------------
__global__ void __launch_bounds__(256, 2)
fat_out_kernel(const __nv_bfloat16* __restrict__ Ah, const __nv_bfloat16* __restrict__ Al,
               const __nv_bfloat16* __restrict__ Bh, const __nv_bfloat16* __restrict__ Bl,
               const float* __restrict__ bias, float* __restrict__ outF,
               float* __restrict__ attn, const float* __restrict__ inv)
{
    if (blockIdx.x < 512) {
        extern __shared__ char smem[];
        int m0 = (blockIdx.x >> 3) * 128, n0 = (blockIdx.x & 7) * 128;
        float acc[4][4][4] = {};
        gemm_core(Ah, Al, 1024, Bh, Bl, 1024, m0, n0, 16, smem, acc);

        int tid = threadIdx.x, wid = tid >> 5, lane = tid & 31;
        int m0w = (wid >> 2) * 64, n0w = (wid & 3) * 32;
        #pragma unroll
        for (int mi = 0; mi < 4; mi++)
            #pragma unroll
            for (int nj = 0; nj < 4; nj++)
                #pragma unroll
                for (int e = 0; e < 4; e++) {
                    int r  = m0 + m0w + mi * 16 + (lane >> 2) + (e >> 1) * 8;
                    int cc = n0 + n0w + nj * 8 + (lane & 3) * 2 + (e & 1);
                    outF[(size_t)r * Dd + cc] = acc[mi][nj][e] + __ldg(bias + cc);
                }
    } else {
        int nb = blockIdx.x - 512;
        size_t row0 = (size_t)nb * 4;
        int tid = threadIdx.x;
        float4* p = (float4*)attn + row0 * (Ss / 4);
        float4 vb[8];
        #pragma unroll
        for (int j = 0; j < 8; j++) vb[j] = p[tid + j * 256];
        #pragma unroll
        for (int j = 0; j < 8; j++) {
            float iv = __ldg(inv + row0 + ((unsigned)(tid + j * 256) >> 9));
            vb[j].x *= iv; vb[j].y *= iv; vb[j].z *= iv; vb[j].w *= iv;
            p[tid + j * 256] = vb[j];
        }
    }
}

// ============ fused attention: sk-tile 64, single-buffered K/V, 2 CTA/SM ======
// smem: QH 0 (16K) | QL 16K | KH 32K (8K) | KL 40K | VH 48K (8K) | VL 56K
//       PH 64K (16K) | PL 80K | RED 96K (1K) | SUM 97K (512B)  total ~97.5K
static constexpr int F_KH  = 32768;
static constexpr int F_KL  = 40960;
static constexpr int F_VH  = 49152;
static constexpr int F_VL  = 57344;
static constexpr int F_PH  = 65536;
static constexpr int F_PL  = 81920;
static constexpr int F_RED = 98304;
static constexpr int F_SUM = 99328;
static constexpr int SMEM_FUSED = 99840;

__global__ void __launch_bounds__(256, 2)
attn_fused_kernel(const __nv_bfloat16* __restrict__ Qh, const __nv_bfloat16* __restrict__ Ql,
                  const __nv_bfloat16* __restrict__ Kh, const __nv_bfloat16* __restrict__ Kl,
                  const __nv_bfloat16* __restrict__ Vth, const __nv_bfloat16* __restrict__ Vtl,
                  const float* __restrict__ mask,
                  float* __restrict__ attn, float* __restrict__ invsum,
                  __nv_bfloat16* __restrict__ Ch, __nv_bfloat16* __restrict__ Cl)
{
    extern __shared__ char smem[];
    const uint32_t sb = smem_u32(smem);
    const int tid = threadIdx.x, wid = tid >> 5, lane = tid & 31;
    // 4x2 warp grid, 32x32 warp tiles (both QK 128x64 and PV 128x64)
    const int m0w = (wid >> 1) * 32, n0w = (wid & 1) * 32;
    const int bh = blockIdx.y, m0 = blockIdx.x * 128;
    const int b = bh >> 4, hh = bh & 15;
    const __nv_bfloat16* Kh_ = Kh + (size_t)bh * Ss * DEPTH;
    const __nv_bfloat16* Kl_ = Kl + (size_t)bh * Ss * DEPTH;
    const __nv_bfloat16* Vh_ = Vth + (size_t)bh * DEPTH * Ss;
    const __nv_bfloat16* Vl_ = Vtl + (size_t)bh * DEPTH * Ss;
    float* RED = (float*)(smem + F_RED);
    float* SUM = (float*)(smem + F_SUM);

    // K tile: 64 rows x 64 k (128B rows). 512 16B-chunks -> 2 per thread.
    auto issueK = [&](int t1) {
        const int sk0n = t1 * 64;
        #pragma unroll
        for (int i = 0; i < 2; i++) {
            int idx = tid + i * 256;
            int r = idx >> 3, sg = idx & 7;
            size_t go = (size_t)(sk0n + r) * 64 + sg * 8;
            uint32_t off = (uint32_t)r * 128 + (((uint32_t)sg ^ (uint32_t)(r & 7)) << 4);
            cpa16(sb + F_KH + off, Kh_ + go);
            cpa16(sb + F_KL + off, Kl_ + go);
        }
        cpa_commit();
    };
    // V^T tile: 64 d-rows x 64 sk (128B rows).
    auto issueV = [&](int t1) {
        const int sk0n = t1 * 64;
        #pragma unroll
        for (int i = 0; i < 2; i++) {
            int idx = tid + i * 256;
            int d = idx >> 3, ch = idx & 7;
            size_t go = (size_t)d * Ss + sk0n + ch * 8;
            uint32_t off = (uint32_t)d * 128 + (((uint32_t)ch ^ (uint32_t)(d & 7)) << 4);
            cpa16(sb + F_VH + off, Vh_ + go);
            cpa16(sb + F_VL + off, Vl_ + go);
        }
        cpa_commit();
    };

    // prologue
    issueK(0);
    issueV(0);
    {
        const __nv_bfloat16* Qh_ = Qh + (size_t)bh * Ss * DEPTH;
        const __nv_bfloat16* Ql_ = Ql + (size_t)bh * Ss * DEPTH;
        #pragma unroll
        for (int i = 0; i < 4; i++) {
            int idx = tid + i * 256;
            int r = idx >> 3, sg = idx & 7;
            size_t go = (size_t)(m0 + r) * 64 + sg * 8;
            uint32_t off = (uint32_t)r * 128 + (((uint32_t)sg ^ (uint32_t)(r & 7)) << 4);
            *(uint4*)(smem + off)         = *(const uint4*)(Qh_ + go);
            *(uint4*)(smem + 16384 + off) = *(const uint4*)(Ql_ + go);
        }
    }
    if (tid < 128) SUM[tid] = 0.f;

    float acc2[2][4][4] = {};   // ctx accumulator (unnormalized), 32x32 per warp

    for (int t = 0; t < 32; t++) {
        const int sk0 = t * 64;

        // wait K(t) (V(t) may still be in flight: 1 pending group allowed)
        cpa_wait<1>();
        __syncthreads();

        // ---- QK tile: 128x64 = Q(128x64) x K(64x64)^T ----
        float acc[2][4][4] = {};
        #pragma unroll
        for (int ks = 0; ks < 4; ks++) {
            uint32_t ah[2][4], al[2][4];
            #pragma unroll
            for (int mi = 0; mi < 2; mi++) {
                int r = m0w + mi * 16 + (lane & 15);
                uint32_t ch = (uint32_t)ks * 2 + (lane >> 4);
                uint32_t ad = (uint32_t)r * 128 + ((ch ^ (uint32_t)(r & 7)) << 4);
                ldsm_x4(ah[mi], sb + ad);
                ldsm_x4(al[mi], sb + 16384 + ad);
            }
            #pragma unroll
            for (int nb = 0; nb < 2; nb++) {
                int n = n0w + nb * 16 + ((lane >> 4) << 3) + (lane & 7);
                uint32_t ch = (uint32_t)ks * 2 + ((lane >> 3) & 1);
                uint32_t bd = (uint32_t)n * 128 + ((ch ^ (uint32_t)(n & 7)) << 4);
                uint32_t bhf[4], blf[4];
                ldsm_x4(bhf, sb + F_KH + bd);
                ldsm_x4(blf, sb + F_KL + bd);
                #pragma unroll
                for (int mi = 0; mi < 2; mi++) {
                    mma16816(acc[mi][nb * 2],     ah[mi], bhf);
                    mma16816(acc[mi][nb * 2 + 1], ah[mi], bhf + 2);
                    mma16816(acc[mi][nb * 2],     ah[mi], blf);
                    mma16816(acc[mi][nb * 2 + 1], ah[mi], blf + 2);
                    mma16816(acc[mi][nb * 2],     al[mi], bhf);
                    mma16816(acc[mi][nb * 2 + 1], al[mi], bhf + 2);
                }
            }
        }
        __syncthreads();           // K consumed
        if (t + 1 < 32) issueK(t + 1);

        // ---- epilogue: e=exp(v), attn write, P stash, rowsum ----
        #pragma unroll
        for (int mi = 0; mi < 2; mi++)
            #pragma unroll
            for (int h = 0; h < 2; h++) {
                int rl = m0w + mi * 16 + (lane >> 2) + h * 8;
                int sq = m0 + rl;
                float rs = 0.f;
                #pragma unroll
                for (int nj = 0; nj < 4; nj++) {
                    int cl = n0w + nj * 8 + (lane & 3) * 2;
                    int sk = sk0 + cl;
                    float v0 = acc[mi][nj][h * 2] * 0.125f
                             + __ldg(mask + (size_t)sq * Ss + sk) * -1e9f;
                    float v1 = acc[mi][nj][h * 2 + 1] * 0.125f
                             + __ldg(mask + (size_t)sq * Ss + sk + 1) * -1e9f;
                    float e0 = __expf(v0), e1 = __expf(v1);
                    rs += e0 + e1;
                    *(float2*)(attn + ((size_t)bh * Ss + sq) * Ss + sk) = make_float2(e0, e1);
                    __nv_bfloat16 h0 = __float2bfloat16(e0);
                    __nv_bfloat16 h1 = __float2bfloat16(e1);
                    __nv_bfloat16 l0 = __float2bfloat16(e0 - __bfloat162float(h0));
                    __nv_bfloat16 l1 = __float2bfloat16(e1 - __bfloat162float(h1));
                    uint32_t off = (uint32_t)rl * 128
                                 + ((((uint32_t)cl >> 3) ^ (uint32_t)(rl & 7)) << 4)
                                 + ((uint32_t)cl & 7) * 2;
                    *(__nv_bfloat162*)(smem + F_PH + off) = __halves2bfloat162(h0, h1);
                    *(__nv_bfloat162*)(smem + F_PL + off) = __halves2bfloat162(l0, l1);
                }
                rs += __shfl_xor_sync(0xffffffffu, rs, 1);
                rs += __shfl_xor_sync(0xffffffffu, rs, 2);
                if ((lane & 3) == 0) RED[(wid & 1) * 128 + rl] = rs;
            }

        // wait V(t): pending groups are {V(t), K(t+1)} -> wait<1>; last iter wait<0>
        if (t + 1 < 32) cpa_wait<1>();
        else            cpa_wait<0>();
        __syncthreads();           // P + RED visible, V ready
        if (tid < 128) SUM[tid] += RED[tid] + RED[128 + tid];

        // ---- PV tile: ctx(128x64) += P(128x64) x V^T(64x64) ----
        #pragma unroll
        for (int ks = 0; ks < 4; ks++) {
            uint32_t pa_h[2][4], pa_l[2][4];
            #pragma unroll
            for (int mi = 0; mi < 2; mi++) {
                int r = m0w + mi * 16 + (lane & 15);
                uint32_t ch = (uint32_t)ks * 2 + (lane >> 4);
                uint32_t ad = (uint32_t)r * 128 + ((ch ^ (uint32_t)(r & 7)) << 4);
                ldsm_x4(pa_h[mi], sb + F_PH + ad);
                ldsm_x4(pa_l[mi], sb + F_PL + ad);
            }
            #pragma unroll
            for (int nbj = 0; nbj < 2; nbj++) {
                int n = n0w + nbj * 16 + ((lane >> 4) << 3) + (lane & 7);
                uint32_t ch = (uint32_t)ks * 2 + ((lane >> 3) & 1);
                uint32_t bd = (uint32_t)n * 128 + ((ch ^ (uint32_t)(n & 7)) << 4);
                uint32_t vh[4], vl[4];
                ldsm_x4(vh, sb + F_VH + bd);
                ldsm_x4(vl, sb + F_VL + bd);
                #pragma unroll
                for (int mi = 0; mi < 2; mi++) {
                    mma16816(acc2[mi][nbj * 2],     pa_h[mi], vh);
                    mma16816(acc2[mi][nbj * 2 + 1], pa_h[mi], vh + 2);
                    mma16816(acc2[mi][nbj * 2],     pa_h[mi], vl);
                    mma16816(acc2[mi][nbj * 2 + 1], pa_h[mi], vl + 2);
                    mma16816(acc2[mi][nbj * 2],     pa_l[mi], vh);
                    mma16816(acc2[mi][nbj * 2 + 1], pa_l[mi], vh + 2);
                }
            }
        }
        __syncthreads();           // V + P consumed
        if (t + 1 < 32) issueV(t + 1);
    }

    if (tid < 128) invsum[(size_t)bh * Ss + m0 + tid] = 1.0f / SUM[tid];

    // ctx epilogue: scale by 1/rowsum -> bf16 hi/lo [b,s,1024]
    #pragma unroll
    for (int mi = 0; mi < 2; mi++)
        #pragma unroll
        for (int e = 0; e < 4; e += 2) {
            int rl = m0w + mi * 16 + (lane >> 2) + (e >> 1) * 8;
            float inv = 1.0f / SUM[rl];
            int s = m0 + rl;
            #pragma unroll
            for (int nj = 0; nj < 4; nj++)
                #pragma unroll
                for (int e2 = 0; e2 < 2; e2++) {
                    int d = n0w + nj * 8 + (lane & 3) * 2 + e2;
                    float v = acc2[mi][nj][e + e2] * inv;
                    __nv_bfloat16 hv = __float2bfloat16(v);
                    __nv_bfloat16 lv = __float2bfloat16(v - __bfloat162float(hv));
                    size_t idx = ((size_t)(b * Ss + s)) * Dd + hh * DEPTH + d;
                    Ch[idx] = hv; Cl[idx] = lv;
                }
        }
}

// ---------------- fat prep: 4 W transposes + 3 activation hi/lo splits ------
__global__ void __launch_bounds__(1024)
prep_kernel(const float* __restrict__ Wq, const float* __restrict__ Wk,
            const float* __restrict__ Wv, const float* __restrict__ Wo,
            const float* __restrict__ q, const float* __restrict__ k,
            const float* __restrict__ v,
            __nv_bfloat16* __restrict__ Wth, __nv_bfloat16* __restrict__ Wtl,
            __nv_bfloat16* __restrict__ Xh,  __nv_bfloat16* __restrict__ Xl)
{
    int bid = blockIdx.x, tid = threadIdx.x;
    if (bid < 4096) {
        __shared__ float t[32][33];
        int w = bid >> 10, idx = bid & 1023;
        int bx = idx & 31, by = idx >> 5;
        const float* W = (w == 0) ? Wq : (w == 1) ? Wk : (w == 2) ? Wv : Wo;
        int tx = tid & 31, ty = tid >> 5;
        t[ty][tx] = W[(size_t)(by * 32 + ty) * Dd + bx * 32 + tx];
        __syncthreads();
        int n = bx * 32 + ty, kk = by * 32 + tx;
        float val = t[tx][ty];
        __nv_bfloat16 hv = __float2bfloat16(val);
        size_t o = (size_t)w * Dd * Dd + (size_t)n * Dd + kk;
        Wth[o] = hv;
        Wtl[o] = __float2bfloat16(val - __bfloat162float(hv));
    } else {
        int i = bid - 4096;
        int tsel = i >> 10, blk = i & 1023;
        const float* X = (tsel == 0) ? q : (tsel == 1) ? k : v;
        size_t base = (size_t)blk * 8192;
        #pragma unroll
        for (int j = 0; j < 2; j++) {
            size_t e = base + ((size_t)tid + j * 1024) * 4;
            float4 f = *(const float4*)(X + e);
            __align__(8) __nv_bfloat16 hb[4], lb[4];
            hb[0] = __float2bfloat16(f.x); lb[0] = __float2bfloat16(f.x - __bfloat162float(hb[0]));
            hb[1] = __float2bfloat16(f.y); lb[1] = __float2bfloat16(f.y - __bfloat162float(hb[1]));
            hb[2] = __float2bfloat16(f.z); lb[2] = __float2bfloat16(f.z - __bfloat162float(hb[2]));
            hb[3] = __float2bfloat16(f.w); lb[3] = __float2bfloat16(f.w - __bfloat162float(hb[3]));
            size_t oo = (size_t)tsel * BS * Dd + e;
            *(uint2*)(Xh + oo) = *(uint2*)hb;
            *(uint2*)(Xl + oo) = *(uint2*)lb;
        }
    }
}

// ---------------------------------------------------------------------------
extern "C" void kernel_launch(void* const* d_in, const int* in_sizes, int n_in,
                              void* d_out, int out_size) {
    const float* q    = (const float*)d_in[0];
    const float* k    = (const float*)d_in[1];
    const float* v    = (const float*)d_in[2];
    const float* mask = (const float*)d_in[3];
    const float* Wq   = (const float*)d_in[4];
    const float* bq   = (const float*)d_in[5];
    const float* Wk   = (const float*)d_in[6];
    const float* bk   = (const float*)d_in[7];
    const float* Wv   = (const float*)d_in[8];
    const float* bv   = (const float*)d_in[9];
    const float* Wo   = (const float*)d_in[10];
    const float* bo   = (const float*)d_in[11];
    float* out = (float*)d_out;

    const size_t OUT_ELEMS  = (size_t)BS * Dd;
    const size_t ATTN_ELEMS = (size_t)BH * Ss * Ss;

    float* attnbuf = nullptr;
    cudaGetSymbolAddress((void**)&attnbuf, g_attn);
    if ((size_t)out_size >= OUT_ELEMS + ATTN_ELEMS) attnbuf = out + OUT_ELEMS;

    __nv_bfloat16 *dWth, *dWtl, *dXh, *dXl;
    __nv_bfloat16 *dQh, *dQl, *dKh, *dKl, *dVth, *dVtl, *dCh, *dCl;
    float* dInv;
    cudaGetSymbolAddress((void**)&dWth, g_Wth);
    cudaGetSymbolAddress((void**)&dWtl, g_Wtl);
    cudaGetSymbolAddress((void**)&dXh,  g_Xh);
    cudaGetSymbolAddress((void**)&dXl,  g_Xl);
    cudaGetSymbolAddress((void**)&dQh,  g_Qh);
    cudaGetSymbolAddress((void**)&dQl,  g_Ql);
    cudaGetSymbolAddress((void**)&dKh,  g_Kh);
    cudaGetSymbolAddress((void**)&dKl,  g_Kl);
    cudaGetSymbolAddress((void**)&dVth, g_Vth);
    cudaGetSymbolAddress((void**)&dVtl, g_Vtl);
    cudaGetSymbolAddress((void**)&dCh,  g_Ch);
    cudaGetSymbolAddress((void**)&dCl,  g_Cl);
    cudaGetSymbolAddress((void**)&dInv, g_inv);

    cudaFuncSetAttribute(proj_kernel,       cudaFuncAttributeMaxDynamicSharedMemorySize, SMEM_PROJ);
    cudaFuncSetAttribute(fat_out_kernel,    cudaFuncAttributeMaxDynamicSharedMemorySize, SMEM_PROJ);
    cudaFuncSetAttribute(attn_fused_kernel, cudaFuncAttributeMaxDynamicSharedMemorySize, SMEM_FUSED);

    const size_t WSZ = (size_t)Dd * Dd;
    const size_t XSZ = (size_t)BS * Dd;
    dim3 projGrid(8, 64);

    prep_kernel<<<7168, 1024>>>(Wq, Wk, Wv, Wo, q, k, v, dWth, dWtl, dXh, dXl);

    proj_kernel<<<projGrid, 256, SMEM_PROJ>>>(dXh,           dXl,           dWth,           dWtl,
                                              bq, dQh, dQl, 1);
    proj_kernel<<<projGrid, 256, SMEM_PROJ>>>(dXh + XSZ,     dXl + XSZ,     dWth + WSZ,     dWtl + WSZ,
                                              bk, dKh, dKl, 1);
    proj_kernel<<<projGrid, 256, SMEM_PROJ>>>(dXh + 2 * XSZ, dXl + 2 * XSZ, dWth + 2 * WSZ, dWtl + 2 * WSZ,
                                              bv, dVth, dVtl, 2);

    attn_fused_kernel<<<dim3(16, 64), 256, SMEM_FUSED>>>(dQh, dQl, dKh, dKl, dVth, dVtl,
                                                         mask, attnbuf, dInv, dCh, dCl);

    fat_out_kernel<<<512 + 32768, 256, SMEM_PROJ>>>(dCh, dCl, dWth + 3 * WSZ, dWtl + 3 * WSZ,
                                                    bo, out, attnbuf, dInv);
}